// round 4
// baseline (speedup 1.0000x reference)
#include <cuda_runtime.h>
#include <math.h>
#include <stdint.h>

#define BB 512
#define TT 64
#define NLL 32
#define LATD 64
#define HIDD 128
#define DIN 65
#define G3 384
#define TMAXV 2000
#define QPADV 2000
#define MAXG 160
#define SCALE_F 365.0f

// ------------------------ device scratch (static, no allocs) ----------------
__device__ float  g_GI[BB*TT*G3];
__device__ float  g_h[BB*HIDD];
__device__ float  g_z0[BB*LATD];
__device__ int    g_pres[TMAXV];
__device__ int    g_rank[TMAXV];
__device__ float  g_qt[QPADV];
__device__ float  g_grid[MAXG];
__device__ int    g_niters;
__device__ int    g_maskmode;
__device__ double g_sse, g_nobs, g_kl;
__device__ float  g_ys[(size_t)MAXG*BB*LATD];

// ------------------------ helpers -------------------------------------------
__device__ __forceinline__ float fsigm(float x){
    return __fdividef(1.0f, 1.0f + __expf(-x));
}
__device__ __forceinline__ float ftanh(float x){
    float e = __expf(-2.0f*fabsf(x));
    float r = __fdividef(1.0f - e, 1.0f + e);
    return __int_as_float(__float_as_int(r) | (__float_as_int(x) & 0x80000000));
}
__device__ __forceinline__ unsigned long long pk2f(float a, float b){
    unsigned long long r;
    asm("mov.b64 %0, {%1, %2};" : "=l"(r) : "f"(a), "f"(b));
    return r;
}
__device__ __forceinline__ unsigned long long ffma2(unsigned long long a,
                                                    unsigned long long b,
                                                    unsigned long long c){
    unsigned long long d;
    asm("fma.rn.f32x2 %0, %1, %2, %3;" : "=l"(d) : "l"(a), "l"(b), "l"(c));
    return d;
}
__device__ __forceinline__ unsigned long long fadd2(unsigned long long a,
                                                    unsigned long long b){
    unsigned long long d;
    asm("add.rn.f32x2 %0, %1, %2;" : "=l"(d) : "l"(a), "l"(b));
    return d;
}
__device__ __forceinline__ float2 upk2f(unsigned long long v){
    float2 f;
    asm("mov.b64 {%0, %1}, %2;" : "=f"(f.x), "=f"(f.y) : "l"(v));
    return f;
}

__device__ __forceinline__ float mread(const void* m, size_t idx, int mode){
    if(mode==0) return ((const unsigned char*)m)[idx] ? 1.0f : 0.0f;
    if(mode==1) return ((const int*)m)[idx]           ? 1.0f : 0.0f;
    return ((const float*)m)[idx] != 0.0f ? 1.0f : 0.0f;
}

// ------------------------ k0: zero state ------------------------------------
__global__ void k_zero(){
    int i = blockIdx.x*blockDim.x + threadIdx.x;
    if(i < TMAXV) g_pres[i] = 0;
    if(i == 0){ g_sse = 0.0; g_nobs = 0.0; g_kl = 0.0; }
}

// ------------------------ k1: detect mask dtype -----------------------------
__global__ void k_detect(const void* m){
    __shared__ int flags[3]; // notF32, hasOne, isU8
    int tid = threadIdx.x;
    if(tid < 3) flags[tid] = 0;
    __syncthreads();
    const unsigned int* w = (const unsigned int*)m;
    int notf = 0, one = 0;
    for(int i = tid; i < 1024; i += 256){
        unsigned v = w[i];
        if(v == 0x3f800000u) one = 1; else if(v != 0u) notf = 1;
    }
    const unsigned char* c = (const unsigned char*)m;
    int u8 = 0;
    for(int i = tid; i < 4096; i += 256){ if((i & 3) && c[i]) u8 = 1; }
    if(notf) atomicOr(&flags[0], 1);
    if(one)  atomicOr(&flags[1], 1);
    if(u8)   atomicOr(&flags[2], 1);
    __syncthreads();
    if(tid == 0){
        if(!flags[0] && flags[1]) g_maskmode = 2;
        else g_maskmode = flags[2] ? 0 : 1;
    }
}

// ------------------------ k2: mark presence ---------------------------------
__global__ void k_mark(const int* __restrict__ tp){
    int i = blockIdx.x*blockDim.x + threadIdx.x;
    if(i < BB*TT){
        int v = tp[i];
        v = min(max(v, 0), TMAXV-1);
        g_pres[v] = 1;
    }
}

// ------------------------ k3: unique/rank/query/grid ------------------------
__global__ void k_build(){
    __shared__ int cnt[256];
    __shared__ int su[QPADV];
    __shared__ int sNU, sNit;
    int tid = threadIdx.x;
    int base = tid*8;
    int c = 0;
    for(int i = 0; i < 8; i++){ int v = base+i; if(v < TMAXV && g_pres[v]) c++; }
    cnt[tid] = c;
    __syncthreads();
    if(tid == 0){
        int run = 0;
        for(int i = 0; i < 256; i++){ int t = cnt[i]; cnt[i] = run; run += t; }
        sNU = run;
    }
    __syncthreads();
    int r = cnt[tid];
    for(int i = 0; i < 8; i++){
        int v = base+i;
        if(v < TMAXV){
            if(g_pres[v]){ g_rank[v] = r; su[r] = v; r++; }
            else g_rank[v] = 0;
        }
    }
    __syncthreads();
    int U = sNU;
    int mx = su[U-1];
    float t0f = (float)su[0]/SCALE_F;
    float t1f = (float)mx/SCALE_F;
    if(tid == 0){
        double nd = ceil(((double)t1f - (double)t0f)/0.05 + 1.0);
        int nit = (int)nd;
        if(nit < 2) nit = 2;
        if(nit > MAXG) nit = MAXG;
        g_niters = nit; sNit = nit;
    }
    __syncthreads();
    int nit = sNit;
    for(int q = tid; q < QPADV; q += 256){
        int v = (q < U) ? su[q] : mx;
        g_qt[q] = (float)v/SCALE_F;
    }
    double t0d = (double)t0f, t1d = (double)t1f;
    for(int i = tid; i < nit; i += 256){
        double gd = (double)i*0.05 + t0d;
        if(i == nit-1 && gd > t1d) gd = t1d;
        g_grid[i] = (float)gd;
    }
}

// ------------------------ k4: GI = x@Wih + bih ------------------------------
#define GITILE 32
__global__ __launch_bounds__(384) void k_gi(const float* __restrict__ obs,
                                            const void* __restrict__ maskp,
                                            const int* __restrict__ tp,
                                            const float* __restrict__ Wih,
                                            const float* __restrict__ bih){
    __shared__ float xs[GITILE][DIN];
    int tid = threadIdx.x;
    int mode = g_maskmode;
    int base = blockIdx.x * GITILE;
    for(int i = tid; i < GITILE*DIN; i += 384){
        int p = i / DIN, d = i - p*DIN;
        int bp = base + p;
        int t = bp & (TT-1);
        float v;
        if(d < NLL){
            float m = mread(maskp, (size_t)bp*NLL + d, mode);
            v = m * obs[(size_t)bp*NLL + d];
        } else if(d < 2*NLL){
            v = mread(maskp, (size_t)bp*NLL + (d-NLL), mode);
        } else {
            v = (t == 0) ? 0.0f : (float)(tp[bp] - tp[bp-1]);
        }
        xs[p][d] = v;
    }
    __syncthreads();
    int j = tid;
    float w[DIN];
    #pragma unroll
    for(int d = 0; d < DIN; d++) w[d] = Wih[d*G3 + j];
    float bj = bih[j];
    for(int p = 0; p < GITILE; p++){
        float acc = bj;
        #pragma unroll
        for(int d = 0; d < DIN; d++) acc = fmaf(xs[p][d], w[d], acc);
        g_GI[(size_t)(base+p)*G3 + j] = acc;
    }
}

// ------------------------ k5: GRU (sequential, 4 rows/CTA, f32x2) -----------
__global__ __launch_bounds__(384,1) void k_gru(const float* __restrict__ Whh,
                                               const float* __restrict__ bhh){
    extern __shared__ float sm[];
    float4* h4    = (float4*)sm;          // 128
    float4* gh4   = h4 + HIDD;            // 384
    float4* gi4   = gh4 + G3;             // 384
    float*  whh_s = (float*)(gi4 + G3);   // 128*384
    int j  = threadIdx.x;
    int b0 = blockIdx.x * 4;
    for(int i = j; i < HIDD*G3; i += 384) whh_s[i] = Whh[i];
    if(j < HIDD) h4[j] = make_float4(0.f,0.f,0.f,0.f);
    float bj = bhh[j];
    const size_t rs = (size_t)TT*G3;
    const float* Gp0 = g_GI + (size_t)(b0+0)*rs;
    const float* Gp1 = g_GI + (size_t)(b0+1)*rs;
    const float* Gp2 = g_GI + (size_t)(b0+2)*rs;
    const float* Gp3 = g_GI + (size_t)(b0+3)*rs;
    const ulonglong2* h2 = (const ulonglong2*)h4;
    __syncthreads();
    for(int s = 0; s < TT; s++){
        int t = TT-1-s;
        size_t off = (size_t)t*G3 + j;
        float gi0 = Gp0[off], gi1 = Gp1[off], gi2 = Gp2[off], gi3 = Gp3[off];
        unsigned long long acc01 = pk2f(0.f, 0.f);
        unsigned long long acc23 = pk2f(0.f, 0.f);
        #pragma unroll 8
        for(int k = 0; k < HIDD; k++){
            ulonglong2 hv = h2[k];
            float w = whh_s[k*G3 + j];
            unsigned long long wd = pk2f(w, w);
            acc01 = ffma2(hv.x, wd, acc01);
            acc23 = ffma2(hv.y, wd, acc23);
        }
        float2 v01 = upk2f(acc01), v23 = upk2f(acc23);
        gh4[j] = make_float4(v01.x+bj, v01.y+bj, v23.x+bj, v23.y+bj);
        gi4[j] = make_float4(gi0, gi1, gi2, gi3);
        __syncthreads();
        if(j < HIDD){
            float4 ir = gi4[j], iz = gi4[j+HIDD], in = gi4[j+2*HIDD];
            float4 hr = gh4[j], hz = gh4[j+HIDD], hn = gh4[j+2*HIDD];
            float4 hv = h4[j];
            { float r = fsigm(ir.x+hr.x), z = fsigm(iz.x+hz.x);
              float n = ftanh(in.x + r*hn.x); hv.x = (1.f-z)*n + z*hv.x; }
            { float r = fsigm(ir.y+hr.y), z = fsigm(iz.y+hz.y);
              float n = ftanh(in.y + r*hn.y); hv.y = (1.f-z)*n + z*hv.y; }
            { float r = fsigm(ir.z+hr.z), z = fsigm(iz.z+hz.z);
              float n = ftanh(in.z + r*hn.z); hv.z = (1.f-z)*n + z*hv.z; }
            { float r = fsigm(ir.w+hr.w), z = fsigm(iz.w+hz.w);
              float n = ftanh(in.w + r*hn.w); hv.w = (1.f-z)*n + z*hv.w; }
            h4[j] = hv;
        }
        __syncthreads();
    }
    if(j < HIDD){
        float4 hv = h4[j];
        g_h[(b0+0)*HIDD + j] = hv.x;
        g_h[(b0+1)*HIDD + j] = hv.y;
        g_h[(b0+2)*HIDD + j] = hv.z;
        g_h[(b0+3)*HIDD + j] = hv.w;
    }
}

// ------------------------ k6: mu/logvar/z0/KL -------------------------------
__global__ __launch_bounds__(64) void k_latent(const float* __restrict__ Wmu,
                                               const float* __restrict__ bmu,
                                               const float* __restrict__ Wlv,
                                               const float* __restrict__ blv,
                                               const float* __restrict__ eps){
    __shared__ float hs[HIDD];
    __shared__ float red[LATD];
    int b = blockIdx.x, tid = threadIdx.x;
    hs[tid] = g_h[b*HIDD + tid];
    hs[tid+64] = g_h[b*HIDD + tid + 64];
    __syncthreads();
    float mu = bmu[tid], lv = blv[tid];
    #pragma unroll 8
    for(int k = 0; k < HIDD; k++){
        float h = hs[k];
        mu = fmaf(h, Wmu[k*LATD + tid], mu);
        lv = fmaf(h, Wlv[k*LATD + tid], lv);
    }
    g_z0[b*LATD + tid] = mu + eps[b*LATD + tid]*expf(0.5f*lv);
    red[tid] = 1.0f + lv - mu*mu - expf(lv);
    __syncthreads();
    if(tid == 0){
        float s = 0.f;
        for(int i = 0; i < LATD; i++) s += red[i];
        atomicAdd(&g_kl, (double)s);
    }
}

// ------------------------ k7: RK4 latent ODE (256 thr, f32x2) ---------------
// SMEM layout (bytes):
//   w2p  : ull [128*128]  packed (w,w)          131072
//   w1s  : f32 [64*128]                          32768
//   w3s  : f32 [128*64]                          32768
//   zin  : f32 [64][4]   (lat, row)               1024
//   a1   : f32 [128][2][2] as float2[(j*2+p)]     2048
//   a2   : f32 [128][4]  (j, row)                 2048
//   ys_  : f32 [64][4]                            1024
//   kc   : f32 [64][4]                            1024
//   b1s/b2s (128 each), b3s (64), gr (160)        1920
#define RK4_SMEM_BYTES (131072 + 32768 + 32768 + 1024 + 2048 + 2048 + 1024 + 1024 + 1920)
__global__ __launch_bounds__(256,1) void k_rk4(const float* __restrict__ W1,
                                               const float* __restrict__ b1,
                                               const float* __restrict__ W2,
                                               const float* __restrict__ b2,
                                               const float* __restrict__ W3,
                                               const float* __restrict__ b3){
    extern __shared__ float sm[];
    unsigned long long* w2p = (unsigned long long*)sm;     // 16384 ull
    float* w1s = (float*)(w2p + 128*128);                  // 8192 f
    float* w3s = w1s + 64*128;                             // 8192 f
    float* zin = w3s + 128*64;                             // 256
    float* a1  = zin + 256;                                // 512
    float* a2  = a1 + 512;                                 // 512
    float* ys_ = a2 + 512;                                 // 256
    float* kc  = ys_ + 256;                                // 256
    float* b1s = kc + 256;                                 // 128
    float* b2s = b1s + 128;                                // 128
    float* b3s = b2s + 128;                                // 64
    float* gr  = b3s + 64;                                 // MAXG
    int tid = threadIdx.x;
    int j   = tid & 127;            // output column (layers 1,2)
    int p   = tid >> 7;             // row-pair 0/1 (warp-uniform)
    int c3  = tid & 63;             // layer3 column
    int q3  = tid >> 6;             // layer3 row 0..3 (warp-uniform)
    for(int i = tid; i < 64*128;  i += 256) w1s[i] = W1[i];
    for(int i = tid; i < 128*128; i += 256){ float w = W2[i]; w2p[i] = pk2f(w, w); }
    for(int i = tid; i < 128*64;  i += 256) w3s[i] = W3[i];
    if(tid < 128){ b1s[tid] = b1[tid]; b2s[tid] = b2[tid]; }
    if(tid < 64)  b3s[tid] = b3[tid];
    int nit = g_niters;
    for(int i = tid; i < nit; i += 256) gr[i] = g_grid[i];
    int b0 = blockIdx.x * 4;
    if(tid < 64){
        int l = tid;
        float z0_ = g_z0[(b0+0)*LATD + l];
        float z1_ = g_z0[(b0+1)*LATD + l];
        float z2_ = g_z0[(b0+2)*LATD + l];
        float z3_ = g_z0[(b0+3)*LATD + l];
        zin[l*4+0] = z0_; zin[l*4+1] = z1_; zin[l*4+2] = z2_; zin[l*4+3] = z3_;
        ys_[l*4+0] = z0_; ys_[l*4+1] = z1_; ys_[l*4+2] = z2_; ys_[l*4+3] = z3_;
        g_ys[(size_t)(b0+0)*LATD + l] = z0_;
        g_ys[(size_t)(b0+1)*LATD + l] = z1_;
        g_ys[(size_t)(b0+2)*LATD + l] = z2_;
        g_ys[(size_t)(b0+3)*LATD + l] = z3_;
    }
    __syncthreads();
    const unsigned long long* zin2 = (const unsigned long long*)zin;
    const unsigned long long* a1u  = (const unsigned long long*)a1;
    float2* a1w = (float2*)a1;
    float2* a2w = (float2*)a2;
    for(int step = 0; step < nit-1; step++){
        float hs = gr[step+1] - gr[step];
        #pragma unroll
        for(int e = 0; e < 4; e++){
            // ---- layer 1: 64 -> 128, tanh (2 rows via f32x2) ----
            unsigned long long accA = pk2f(b1s[j], b1s[j]);
            unsigned long long accB = pk2f(0.f, 0.f);
            #pragma unroll 8
            for(int k = 0; k < 64; k += 2){
                float wa = w1s[k*128 + j];
                float wb = w1s[(k+1)*128 + j];
                accA = ffma2(zin2[k*2 + p],     pk2f(wa, wa), accA);
                accB = ffma2(zin2[(k+1)*2 + p], pk2f(wb, wb), accB);
            }
            float2 a = upk2f(fadd2(accA, accB));
            a1w[j*2 + p] = make_float2(ftanh(a.x), ftanh(a.y));
            __syncthreads();
            // ---- layer 2: 128 -> 128, tanh (packed weights) ----
            unsigned long long bA = pk2f(b2s[j], b2s[j]);
            unsigned long long bB = pk2f(0.f, 0.f);
            #pragma unroll 8
            for(int k = 0; k < 128; k += 2){
                bA = ffma2(a1u[k*2 + p],     w2p[k*128 + j],     bA);
                bB = ffma2(a1u[(k+1)*2 + p], w2p[(k+1)*128 + j], bB);
            }
            float2 bb = upk2f(fadd2(bA, bB));
            a2w[j*2 + p] = make_float2(ftanh(bb.x), ftanh(bb.y));
            __syncthreads();
            // ---- layer 3: 128 -> 64 (1 row per thread, 4 rows total) ----
            float fA = b3s[c3], fB = 0.f;
            #pragma unroll 8
            for(int k = 0; k < 128; k += 2){
                fA = fmaf(a2[k*4 + q3],     w3s[k*64 + c3],     fA);
                fB = fmaf(a2[(k+1)*4 + q3], w3s[(k+1)*64 + c3], fB);
            }
            float f = fA + fB;
            // ---- RK4 combine: thread owns (lat c3, row q3) ----
            int idx = c3*4 + q3;
            float yv = ys_[idx];
            if(e == 0){
                kc[idx] = f;
                zin[idx] = yv + 0.5f*hs*f;
            } else if(e == 1){
                kc[idx] += 2.0f*f;
                zin[idx] = yv + 0.5f*hs*f;
            } else if(e == 2){
                kc[idx] += 2.0f*f;
                zin[idx] = yv + hs*f;
            } else {
                float yn = yv + (hs/6.0f)*(kc[idx] + f);
                ys_[idx] = yn;
                zin[idx] = yn;
                g_ys[((size_t)(step+1)*BB + b0 + q3)*LATD + c3] = yn;
            }
            __syncthreads();
        }
    }
}

// ------------------------ interp helper -------------------------------------
__device__ __forceinline__ void interp_coeff(float qt, int nit, int* gi_out, float* w_out){
    int lo = 0, hi = nit;
    while(lo < hi){
        int mid = (lo + hi) >> 1;
        if(g_grid[mid] <= qt) lo = mid + 1; else hi = mid;
    }
    int gi = lo - 1;
    gi = max(0, min(gi, nit-2));
    float tl = g_grid[gi], tr = g_grid[gi+1];
    float den = tr - tl; if(den == 0.0f) den = 1.0f;
    *gi_out = gi;
    *w_out = (qt - tl) / den;
}

// ------------------------ k8: recon loss ------------------------------------
__global__ __launch_bounds__(128) void k_recon(const float* __restrict__ Wo1,
                                               const float* __restrict__ bo1,
                                               const float* __restrict__ Wo2,
                                               const float* __restrict__ bo2,
                                               const float* __restrict__ obs,
                                               const void* __restrict__ maskp,
                                               const int* __restrict__ tp,
                                               const int* __restrict__ seq_lens){
    extern __shared__ float sm[];
    float* wo1s = sm;                 // 64*128
    float* wo2s = wo1s + 64*128;      // 128*32
    float* bo1s = wo2s + 128*32;      // 128
    float* bo2s = bo1s + 128;         // 32
    float* zs   = bo2s + 32;          // 64*64
    float* h1s  = zs + TT*LATD;       // 128
    float* tw   = h1s + 128;          // 64
    int*   tgi  = (int*)(tw + TT);    // 64
    int tid = threadIdx.x, b = blockIdx.x;
    int mode = g_maskmode;
    for(int i = tid; i < 64*128; i += 128) wo1s[i] = Wo1[i];
    for(int i = tid; i < 128*32; i += 128) wo2s[i] = Wo2[i];
    bo1s[tid] = bo1[tid];
    if(tid < 32) bo2s[tid] = bo2[tid];
    int nit = g_niters;
    if(tid < TT){
        int v = tp[b*TT + tid];
        v = min(max(v, 0), TMAXV-1);
        float qt = g_qt[g_rank[v]];
        int gi; float w;
        interp_coeff(qt, nit, &gi, &w);
        tgi[tid] = gi; tw[tid] = w;
    }
    __syncthreads();
    for(int i = tid; i < TT*LATD; i += 128){
        int t = i >> 6, l = i & 63;
        int gi = tgi[t]; float w = tw[t];
        float zl = g_ys[((size_t)gi*BB + b)*LATD + l];
        float zr = g_ys[((size_t)(gi+1)*BB + b)*LATD + l];
        zs[i] = zl*(1.0f - w) + zr*w;
    }
    __syncthreads();
    int sl = seq_lens[b];
    if(sl > TT) sl = TT;
    double lsse = 0.0; float lnm = 0.0f;
    for(int t = 0; t < sl; t++){
        float acc = bo1s[tid];
        #pragma unroll 8
        for(int k = 0; k < 64; k++) acc = fmaf(zs[t*64+k], wo1s[k*128 + tid], acc);
        h1s[tid] = fmaxf(acc, 0.0f);
        __syncthreads();
        if(tid < NLL){
            float o = bo2s[tid];
            #pragma unroll 8
            for(int k = 0; k < 128; k++) o = fmaf(h1s[k], wo2s[k*32 + tid], o);
            float m = mread(maskp, (size_t)(b*TT + t)*NLL + tid, mode);
            float d = o - obs[(size_t)(b*TT + t)*NLL + tid];
            lsse += (double)(m*d*d);
            lnm  += m;
        }
        __syncthreads();
    }
    if(tid < 32){
        #pragma unroll
        for(int o = 16; o > 0; o >>= 1){
            lsse += __shfl_down_sync(0xffffffffu, lsse, o);
            lnm  += __shfl_down_sync(0xffffffffu, lnm,  o);
        }
        if(tid == 0){
            atomicAdd(&g_sse, lsse);
            atomicAdd(&g_nobs, (double)lnm);
        }
    }
}

// ------------------------ k9: z_eval + hazard -------------------------------
__global__ __launch_bounds__(128) void k_hazard(const float* __restrict__ Ws1,
                                                const float* __restrict__ bs1,
                                                const float* __restrict__ Ws2,
                                                const float* __restrict__ bs2,
                                                const float* __restrict__ age,
                                                const int* __restrict__ tp,
                                                const int* __restrict__ seq_lens,
                                                float* __restrict__ out){
    __shared__ float zev[DIN];    // z_eval (64) + age (1)
    __shared__ float hbuf[HIDD];
    int tid = threadIdx.x, b = blockIdx.x;
    int nit = g_niters;
    int sl = seq_lens[b];
    if(sl < 1) sl = 1; if(sl > TT) sl = TT;
    int v = tp[b*TT + sl - 1];
    v = min(max(v, 0), TMAXV-1);
    float qt = g_qt[g_rank[v]];
    int gi; float w;
    interp_coeff(qt, nit, &gi, &w);
    if(tid < LATD){
        float zl = g_ys[((size_t)gi*BB + b)*LATD + tid];
        float zr = g_ys[((size_t)(gi+1)*BB + b)*LATD + tid];
        float z = zl*(1.0f - w) + zr*w;
        zev[tid] = z;
        out[1026 + b*LATD + tid] = z;   // z_eval output
    }
    if(tid == 0) zev[LATD] = age[b];
    __syncthreads();
    float acc = bs1[tid];
    #pragma unroll 8
    for(int k = 0; k < DIN; k++) acc = fmaf(zev[k], Ws1[k*HIDD + tid], acc);
    hbuf[tid] = fmaxf(acc, 0.0f);
    __syncthreads();
    if(tid < 2){
        float o = bs2[tid];
        #pragma unroll 8
        for(int k = 0; k < HIDD; k++) o = fmaf(hbuf[k], Ws2[k*2 + tid], o);
        out[b*2 + tid] = o;             // log_hazard output
    }
}

// ------------------------ k10: write scalars --------------------------------
__global__ void k_final(float* __restrict__ out){
    if(threadIdx.x == 0){
        double n = g_nobs;
        out[1024] = (n > 0.0) ? (float)(g_sse / fmax(n, 1.0)) : 0.0f;   // recon
        out[1025] = (float)(-0.5 * g_kl / (double)BB);                   // kl
    }
}

// ------------------------ launch --------------------------------------------
extern "C" void kernel_launch(void* const* d_in, const int* in_sizes, int n_in,
                              void* d_out, int out_size){
    (void)in_sizes; (void)n_in; (void)out_size;
    const float* obs = (const float*)d_in[0];
    const float* age = (const float*)d_in[1];
    const float* eps = (const float*)d_in[2];
    const float* Wih = (const float*)d_in[3];
    const float* Whh = (const float*)d_in[4];
    const float* bih = (const float*)d_in[5];
    const float* bhh = (const float*)d_in[6];
    const float* Wmu = (const float*)d_in[7];
    const float* bmu = (const float*)d_in[8];
    const float* Wlv = (const float*)d_in[9];
    const float* blv = (const float*)d_in[10];
    const float* W1  = (const float*)d_in[11];
    const float* b1  = (const float*)d_in[12];
    const float* W2  = (const float*)d_in[13];
    const float* b2  = (const float*)d_in[14];
    const float* W3  = (const float*)d_in[15];
    const float* b3  = (const float*)d_in[16];
    const float* Wo1 = (const float*)d_in[17];
    const float* bo1 = (const float*)d_in[18];
    const float* Wo2 = (const float*)d_in[19];
    const float* bo2 = (const float*)d_in[20];
    const float* Ws1 = (const float*)d_in[21];
    const float* bs1 = (const float*)d_in[22];
    const float* Ws2 = (const float*)d_in[23];
    const float* bs2 = (const float*)d_in[24];
    const void*  msk = d_in[25];
    const int*   tp  = (const int*)d_in[26];
    const int*   seq = (const int*)d_in[27];
    float* out = (float*)d_out;

    const int GRU_SMEM = (HIDD + 2*G3)*16 + HIDD*G3*4;            // 210944
    const int RK4_SMEM = RK4_SMEM_BYTES;                          // 205696
    const int REC_SMEM = (64*128 + 128*32 + 128 + 32 + TT*LATD + 128 + TT)*4
                         + TT*4;                                   // ~67328

    cudaFuncSetAttribute(k_gru,   cudaFuncAttributeMaxDynamicSharedMemorySize, GRU_SMEM);
    cudaFuncSetAttribute(k_rk4,   cudaFuncAttributeMaxDynamicSharedMemorySize, RK4_SMEM);
    cudaFuncSetAttribute(k_recon, cudaFuncAttributeMaxDynamicSharedMemorySize, REC_SMEM);

    k_zero  <<<9, 256>>>();
    k_detect<<<1, 256>>>(msk);
    k_mark  <<<(BB*TT + 255)/256, 256>>>(tp);
    k_build <<<1, 256>>>();
    k_gi    <<<BB*TT/GITILE, 384>>>(obs, msk, tp, Wih, bih);
    k_gru   <<<BB/4, 384, GRU_SMEM>>>(Whh, bhh);
    k_latent<<<BB, 64>>>(Wmu, bmu, Wlv, blv, eps);
    k_rk4   <<<BB/4, 256, RK4_SMEM>>>(W1, b1, W2, b2, W3, b3);
    k_recon <<<BB, 128, REC_SMEM>>>(Wo1, bo1, Wo2, bo2, obs, msk, tp, seq);
    k_hazard<<<BB, 128>>>(Ws1, bs1, Ws2, bs2, age, tp, seq, out);
    k_final <<<1, 32>>>(out);
}

// round 6
// speedup vs baseline: 1.3609x; 1.3609x over previous
#include <cuda_runtime.h>
#include <math.h>
#include <stdint.h>

#define BB 512
#define TT 64
#define NLL 32
#define LATD 64
#define HIDD 128
#define DIN 65
#define G3 384
#define TMAXV 2000
#define QPADV 2000
#define MAXG 160
#define SCALE_F 365.0f

// ------------------------ device scratch (static, no allocs) ----------------
__device__ float  g_GI[BB*TT*G3];
__device__ float  g_h[BB*HIDD];
__device__ float  g_z0[BB*LATD];
__device__ int    g_pres[TMAXV];
__device__ int    g_rank[TMAXV];
__device__ float  g_qt[QPADV];
__device__ float  g_grid[MAXG];
__device__ int    g_niters;
__device__ int    g_maskmode;
__device__ double g_sse, g_nobs, g_kl;
__device__ float  g_ys[(size_t)MAXG*BB*LATD];

// ------------------------ helpers -------------------------------------------
__device__ __forceinline__ float fsigm(float x){
    return __fdividef(1.0f, 1.0f + __expf(-x));
}
__device__ __forceinline__ float ftanh(float x){
    float e = __expf(-2.0f*fabsf(x));
    float r = __fdividef(1.0f - e, 1.0f + e);
    return __int_as_float(__float_as_int(r) | (__float_as_int(x) & 0x80000000));
}
__device__ __forceinline__ unsigned long long pk2f(float a, float b){
    unsigned long long r;
    asm("mov.b64 %0, {%1, %2};" : "=l"(r) : "f"(a), "f"(b));
    return r;
}
__device__ __forceinline__ unsigned long long ffma2(unsigned long long a,
                                                    unsigned long long b,
                                                    unsigned long long c){
    unsigned long long d;
    asm("fma.rn.f32x2 %0, %1, %2, %3;" : "=l"(d) : "l"(a), "l"(b), "l"(c));
    return d;
}
__device__ __forceinline__ float hadd2(unsigned long long v){
    float2 f;
    asm("mov.b64 {%0, %1}, %2;" : "=f"(f.x), "=f"(f.y) : "l"(v));
    return f.x + f.y;
}

__device__ __forceinline__ float mread(const void* m, size_t idx, int mode){
    if(mode==0) return ((const unsigned char*)m)[idx] ? 1.0f : 0.0f;
    if(mode==1) return ((const int*)m)[idx]           ? 1.0f : 0.0f;
    return ((const float*)m)[idx] != 0.0f ? 1.0f : 0.0f;
}

// ------------------------ k0: zero state ------------------------------------
__global__ void k_zero(){
    int i = blockIdx.x*blockDim.x + threadIdx.x;
    if(i < TMAXV) g_pres[i] = 0;
    if(i == 0){ g_sse = 0.0; g_nobs = 0.0; g_kl = 0.0; }
}

// ------------------------ k1: detect mask dtype -----------------------------
__global__ void k_detect(const void* m){
    __shared__ int flags[3]; // notF32, hasOne, isU8
    int tid = threadIdx.x;
    if(tid < 3) flags[tid] = 0;
    __syncthreads();
    const unsigned int* w = (const unsigned int*)m;
    int notf = 0, one = 0;
    for(int i = tid; i < 1024; i += 256){
        unsigned v = w[i];
        if(v == 0x3f800000u) one = 1; else if(v != 0u) notf = 1;
    }
    const unsigned char* c = (const unsigned char*)m;
    int u8 = 0;
    for(int i = tid; i < 4096; i += 256){ if((i & 3) && c[i]) u8 = 1; }
    if(notf) atomicOr(&flags[0], 1);
    if(one)  atomicOr(&flags[1], 1);
    if(u8)   atomicOr(&flags[2], 1);
    __syncthreads();
    if(tid == 0){
        if(!flags[0] && flags[1]) g_maskmode = 2;
        else g_maskmode = flags[2] ? 0 : 1;
    }
}

// ------------------------ k2: mark presence ---------------------------------
__global__ void k_mark(const int* __restrict__ tp){
    int i = blockIdx.x*blockDim.x + threadIdx.x;
    if(i < BB*TT){
        int v = tp[i];
        v = min(max(v, 0), TMAXV-1);
        g_pres[v] = 1;
    }
}

// ------------------------ k3: unique/rank/query/grid ------------------------
__global__ void k_build(){
    __shared__ int cnt[256];
    __shared__ int su[QPADV];
    __shared__ int sNU, sNit;
    int tid = threadIdx.x;
    int base = tid*8;
    int c = 0;
    for(int i = 0; i < 8; i++){ int v = base+i; if(v < TMAXV && g_pres[v]) c++; }
    cnt[tid] = c;
    __syncthreads();
    if(tid == 0){
        int run = 0;
        for(int i = 0; i < 256; i++){ int t = cnt[i]; cnt[i] = run; run += t; }
        sNU = run;
    }
    __syncthreads();
    int r = cnt[tid];
    for(int i = 0; i < 8; i++){
        int v = base+i;
        if(v < TMAXV){
            if(g_pres[v]){ g_rank[v] = r; su[r] = v; r++; }
            else g_rank[v] = 0;
        }
    }
    __syncthreads();
    int U = sNU;
    int mx = su[U-1];
    float t0f = (float)su[0]/SCALE_F;
    float t1f = (float)mx/SCALE_F;
    if(tid == 0){
        double nd = ceil(((double)t1f - (double)t0f)/0.05 + 1.0);
        int nit = (int)nd;
        if(nit < 2) nit = 2;
        if(nit > MAXG) nit = MAXG;
        g_niters = nit; sNit = nit;
    }
    __syncthreads();
    int nit = sNit;
    for(int q = tid; q < QPADV; q += 256){
        int v = (q < U) ? su[q] : mx;
        g_qt[q] = (float)v/SCALE_F;
    }
    double t0d = (double)t0f, t1d = (double)t1f;
    for(int i = tid; i < nit; i += 256){
        double gd = (double)i*0.05 + t0d;
        if(i == nit-1 && gd > t1d) gd = t1d;
        g_grid[i] = (float)gd;
    }
}

// ------------------------ k4: GI = x@Wih + bih ------------------------------
#define GITILE 32
__global__ __launch_bounds__(384) void k_gi(const float* __restrict__ obs,
                                            const void* __restrict__ maskp,
                                            const int* __restrict__ tp,
                                            const float* __restrict__ Wih,
                                            const float* __restrict__ bih){
    __shared__ float xs[GITILE][DIN];
    int tid = threadIdx.x;
    int mode = g_maskmode;
    int base = blockIdx.x * GITILE;
    for(int i = tid; i < GITILE*DIN; i += 384){
        int p = i / DIN, d = i - p*DIN;
        int bp = base + p;
        int t = bp & (TT-1);
        float v;
        if(d < NLL){
            float m = mread(maskp, (size_t)bp*NLL + d, mode);
            v = m * obs[(size_t)bp*NLL + d];
        } else if(d < 2*NLL){
            v = mread(maskp, (size_t)bp*NLL + (d-NLL), mode);
        } else {
            v = (t == 0) ? 0.0f : (float)(tp[bp] - tp[bp-1]);
        }
        xs[p][d] = v;
    }
    __syncthreads();
    int j = tid;
    float w[DIN];
    #pragma unroll
    for(int d = 0; d < DIN; d++) w[d] = Wih[d*G3 + j];
    float bj = bih[j];
    for(int p = 0; p < GITILE; p++){
        float acc = bj;
        #pragma unroll
        for(int d = 0; d < DIN; d++) acc = fmaf(xs[p][d], w[d], acc);
        g_GI[(size_t)(base+p)*G3 + j] = acc;
    }
}

// ------------------------ k5: GRU (k-packed f32x2, 4 rows/CTA) --------------
// SMEM: whhp ull[64*384] (k-pair packed Whh, 192KB), gh4/gi4 float4[384], hrow f[4*128]
#define GRU_SMEM_BYTES (64*384*8 + 384*16 + 384*16 + 4*128*4)
__global__ __launch_bounds__(384,1) void k_gru(const float* __restrict__ Whh,
                                               const float* __restrict__ bhh){
    extern __shared__ float sm[];
    unsigned long long* whhp = (unsigned long long*)sm;          // 64*384
    float4* gh4 = (float4*)(whhp + 64*384);                      // 384
    float4* gi4 = gh4 + G3;                                      // 384
    float*  hrow = (float*)(gi4 + G3);                           // 4*128
    int j  = threadIdx.x;
    int b0 = blockIdx.x * 4;
    // pack Whh along k: whhp[kp*384 + j] = (Whh[2kp][j], Whh[2kp+1][j])
    for(int i = j; i < 64*G3; i += 384){
        int kp = i / G3, c = i - kp*G3;
        whhp[i] = pk2f(Whh[(2*kp)*G3 + c], Whh[(2*kp+1)*G3 + c]);
    }
    for(int i = j; i < 4*HIDD; i += 384) hrow[i] = 0.0f;
    float bj = bhh[j];
    const size_t rs = (size_t)TT*G3;
    const float* Gp0 = g_GI + (size_t)(b0+0)*rs;
    const float* Gp1 = g_GI + (size_t)(b0+1)*rs;
    const float* Gp2 = g_GI + (size_t)(b0+2)*rs;
    const float* Gp3 = g_GI + (size_t)(b0+3)*rs;
    const unsigned long long* hu = (const unsigned long long*)hrow; // [r*64 + kp]
    __syncthreads();
    for(int s = 0; s < TT; s++){
        int t = TT-1-s;
        size_t off = (size_t)t*G3 + j;
        float gi0 = Gp0[off], gi1 = Gp1[off], gi2 = Gp2[off], gi3 = Gp3[off];
        unsigned long long a0 = pk2f(0.f,0.f), a1 = a0, a2 = a0, a3 = a0;
        #pragma unroll 8
        for(int kp = 0; kp < 64; kp++){
            unsigned long long w = whhp[kp*G3 + j];
            a0 = ffma2(hu[kp],       w, a0);
            a1 = ffma2(hu[64 + kp],  w, a1);
            a2 = ffma2(hu[128 + kp], w, a2);
            a3 = ffma2(hu[192 + kp], w, a3);
        }
        gh4[j] = make_float4(hadd2(a0)+bj, hadd2(a1)+bj, hadd2(a2)+bj, hadd2(a3)+bj);
        gi4[j] = make_float4(gi0, gi1, gi2, gi3);
        __syncthreads();
        if(j < HIDD){
            float4 ir = gi4[j], iz = gi4[j+HIDD], in = gi4[j+2*HIDD];
            float4 hr = gh4[j], hz = gh4[j+HIDD], hn = gh4[j+2*HIDD];
            float h0 = hrow[j], h1 = hrow[HIDD+j], h2 = hrow[2*HIDD+j], h3 = hrow[3*HIDD+j];
            { float r = fsigm(ir.x+hr.x), z = fsigm(iz.x+hz.x);
              float n = ftanh(in.x + r*hn.x); hrow[j]        = (1.f-z)*n + z*h0; }
            { float r = fsigm(ir.y+hr.y), z = fsigm(iz.y+hz.y);
              float n = ftanh(in.y + r*hn.y); hrow[HIDD+j]   = (1.f-z)*n + z*h1; }
            { float r = fsigm(ir.z+hr.z), z = fsigm(iz.z+hz.z);
              float n = ftanh(in.z + r*hn.z); hrow[2*HIDD+j] = (1.f-z)*n + z*h2; }
            { float r = fsigm(ir.w+hr.w), z = fsigm(iz.w+hz.w);
              float n = ftanh(in.w + r*hn.w); hrow[3*HIDD+j] = (1.f-z)*n + z*h3; }
        }
        __syncthreads();
    }
    if(j < HIDD){
        g_h[(b0+0)*HIDD + j] = hrow[j];
        g_h[(b0+1)*HIDD + j] = hrow[HIDD+j];
        g_h[(b0+2)*HIDD + j] = hrow[2*HIDD+j];
        g_h[(b0+3)*HIDD + j] = hrow[3*HIDD+j];
    }
}

// ------------------------ k6: mu/logvar/z0/KL -------------------------------
__global__ __launch_bounds__(64) void k_latent(const float* __restrict__ Wmu,
                                               const float* __restrict__ bmu,
                                               const float* __restrict__ Wlv,
                                               const float* __restrict__ blv,
                                               const float* __restrict__ eps){
    __shared__ float hs[HIDD];
    __shared__ float red[LATD];
    int b = blockIdx.x, tid = threadIdx.x;
    hs[tid] = g_h[b*HIDD + tid];
    hs[tid+64] = g_h[b*HIDD + tid + 64];
    __syncthreads();
    float mu = bmu[tid], lv = blv[tid];
    #pragma unroll 8
    for(int k = 0; k < HIDD; k++){
        float h = hs[k];
        mu = fmaf(h, Wmu[k*LATD + tid], mu);
        lv = fmaf(h, Wlv[k*LATD + tid], lv);
    }
    g_z0[b*LATD + tid] = mu + eps[b*LATD + tid]*expf(0.5f*lv);
    red[tid] = 1.0f + lv - mu*mu - expf(lv);
    __syncthreads();
    if(tid == 0){
        float s = 0.f;
        for(int i = 0; i < LATD; i++) s += red[i];
        atomicAdd(&g_kl, (double)s);
    }
}

// ------------------------ k7: RK4 latent ODE (k-packed f32x2, 128 thr) ------
// SMEM (bytes): w1p 32768 | w2p 65536 | w3p 32768 | zrow 1024 | a1 2048 |
//               a2 2048 | ys 1024 | kc 1024 | b1s 512 | b2s 512 | b3s 256 | gr 640
#define RK4_SMEM_BYTES (32768 + 65536 + 32768 + 1024 + 2048 + 2048 + 1024 + 1024 + 512 + 512 + 256 + 640)
__global__ __launch_bounds__(128,1) void k_rk4(const float* __restrict__ W1,
                                               const float* __restrict__ b1,
                                               const float* __restrict__ W2,
                                               const float* __restrict__ b2,
                                               const float* __restrict__ W3,
                                               const float* __restrict__ b3){
    extern __shared__ float sm[];
    unsigned long long* w1p = (unsigned long long*)sm;       // 32*128
    unsigned long long* w2p = w1p + 32*128;                  // 64*128
    unsigned long long* w3p = w2p + 64*128;                  // 64*64
    float* zrow = (float*)(w3p + 64*64);                     // 4*64  [r*64+k]
    float* a1   = zrow + 4*64;                               // 4*128 [r*128+k]
    float* a2   = a1 + 4*128;                                // 4*128
    float* ys_  = a2 + 4*128;                                // 4*64
    float* kc   = ys_ + 4*64;                                // 4*64
    float* b1s  = kc + 4*64;                                 // 128
    float* b2s  = b1s + 128;                                 // 128
    float* b3s  = b2s + 128;                                 // 64
    float* gr   = b3s + 64;                                  // MAXG
    int tid = threadIdx.x;
    int j   = tid;            // column for layers 1,2
    int c3  = tid & 63;       // layer-3 column
    int rp  = tid >> 6;       // layer-3 row-pair (rows 2rp, 2rp+1), warp-uniform
    // pack weights along k
    for(int i = tid; i < 32*128; i += 128){
        int kp = i >> 7, c = i & 127;
        w1p[i] = pk2f(W1[(2*kp)*128 + c], W1[(2*kp+1)*128 + c]);
    }
    for(int i = tid; i < 64*128; i += 128){
        int kp = i >> 7, c = i & 127;
        w2p[i] = pk2f(W2[(2*kp)*128 + c], W2[(2*kp+1)*128 + c]);
    }
    for(int i = tid; i < 64*64; i += 128){
        int kp = i >> 6, c = i & 63;
        w3p[i] = pk2f(W3[(2*kp)*64 + c], W3[(2*kp+1)*64 + c]);
    }
    b1s[tid] = b1[tid];
    b2s[tid] = b2[tid];
    if(tid < 64) b3s[tid] = b3[tid];
    int nit = g_niters;
    for(int i = tid; i < nit; i += 128) gr[i] = g_grid[i];
    int b0 = blockIdx.x * 4;
    if(tid < 64){
        int l = tid;
        #pragma unroll
        for(int r = 0; r < 4; r++){
            float z = g_z0[(b0+r)*LATD + l];
            zrow[r*64 + l] = z;
            ys_[r*64 + l] = z;
            g_ys[(size_t)(b0+r)*LATD + l] = z;
        }
    }
    __syncthreads();
    const unsigned long long* zu  = (const unsigned long long*)zrow; // [r*32+kp]
    const unsigned long long* a1u = (const unsigned long long*)a1;   // [r*64+kp]
    const unsigned long long* a2u = (const unsigned long long*)a2;   // [r*64+kp]
    for(int step = 0; step < nit-1; step++){
        float hs = gr[step+1] - gr[step];
        #pragma unroll
        for(int e = 0; e < 4; e++){
            // ---- layer 1: 64 -> 128, tanh; thread j computes 4 rows ----
            {
                unsigned long long q0 = pk2f(b1s[j], 0.f);
                unsigned long long q1 = pk2f(0.f, 0.f), q2 = q1, q3 = q1;
                #pragma unroll 8
                for(int kp = 0; kp < 32; kp++){
                    unsigned long long w = w1p[kp*128 + j];
                    q0 = ffma2(zu[kp],      w, q0);
                    q1 = ffma2(zu[32+kp],   w, q1);
                    q2 = ffma2(zu[64+kp],   w, q2);
                    q3 = ffma2(zu[96+kp],   w, q3);
                }
                float bb = b1s[j];
                a1[j]        = ftanh(hadd2(q0));
                a1[128+j]    = ftanh(hadd2(q1) + bb);
                a1[256+j]    = ftanh(hadd2(q2) + bb);
                a1[384+j]    = ftanh(hadd2(q3) + bb);
            }
            __syncthreads();
            // ---- layer 2: 128 -> 128, tanh ----
            {
                unsigned long long q0 = pk2f(b2s[j], 0.f);
                unsigned long long q1 = pk2f(0.f, 0.f), q2 = q1, q3 = q1;
                #pragma unroll 8
                for(int kp = 0; kp < 64; kp++){
                    unsigned long long w = w2p[kp*128 + j];
                    q0 = ffma2(a1u[kp],      w, q0);
                    q1 = ffma2(a1u[64+kp],   w, q1);
                    q2 = ffma2(a1u[128+kp],  w, q2);
                    q3 = ffma2(a1u[192+kp],  w, q3);
                }
                float bb = b2s[j];
                a2[j]        = ftanh(hadd2(q0));
                a2[128+j]    = ftanh(hadd2(q1) + bb);
                a2[256+j]    = ftanh(hadd2(q2) + bb);
                a2[384+j]    = ftanh(hadd2(q3) + bb);
            }
            __syncthreads();
            // ---- layer 3: 128 -> 64 (no act); thread (c3, rp) does rows 2rp,2rp+1
            {
                int r0 = 2*rp, r1 = 2*rp+1;
                unsigned long long qa0 = pk2f(b3s[c3], 0.f);
                unsigned long long qb0 = pk2f(0.f, 0.f);
                unsigned long long qa1 = pk2f(b3s[c3], 0.f);
                unsigned long long qb1 = pk2f(0.f, 0.f);
                const unsigned long long* ar0 = a2u + r0*64;
                const unsigned long long* ar1 = a2u + r1*64;
                #pragma unroll 8
                for(int kp = 0; kp < 64; kp += 2){
                    unsigned long long wA = w3p[kp*64 + c3];
                    unsigned long long wB = w3p[(kp+1)*64 + c3];
                    qa0 = ffma2(ar0[kp],   wA, qa0);
                    qa1 = ffma2(ar1[kp],   wA, qa1);
                    qb0 = ffma2(ar0[kp+1], wB, qb0);
                    qb1 = ffma2(ar1[kp+1], wB, qb1);
                }
                float f0 = hadd2(qa0) + hadd2(qb0);
                float f1 = hadd2(qa1) + hadd2(qb1);
                // ---- RK4 combine ----
                int i0 = r0*64 + c3, i1 = r1*64 + c3;
                float y0 = ys_[i0], y1 = ys_[i1];
                if(e == 0){
                    kc[i0] = f0;               kc[i1] = f1;
                    zrow[i0] = y0 + 0.5f*hs*f0; zrow[i1] = y1 + 0.5f*hs*f1;
                } else if(e == 1){
                    kc[i0] += 2.0f*f0;         kc[i1] += 2.0f*f1;
                    zrow[i0] = y0 + 0.5f*hs*f0; zrow[i1] = y1 + 0.5f*hs*f1;
                } else if(e == 2){
                    kc[i0] += 2.0f*f0;         kc[i1] += 2.0f*f1;
                    zrow[i0] = y0 + hs*f0;      zrow[i1] = y1 + hs*f1;
                } else {
                    float h6 = hs/6.0f;
                    float yn0 = y0 + h6*(kc[i0] + f0);
                    float yn1 = y1 + h6*(kc[i1] + f1);
                    ys_[i0] = yn0; ys_[i1] = yn1;
                    zrow[i0] = yn0; zrow[i1] = yn1;
                    g_ys[((size_t)(step+1)*BB + b0 + r0)*LATD + c3] = yn0;
                    g_ys[((size_t)(step+1)*BB + b0 + r1)*LATD + c3] = yn1;
                }
            }
            __syncthreads();
        }
    }
}

// ------------------------ interp helper -------------------------------------
__device__ __forceinline__ void interp_coeff(float qt, int nit, int* gi_out, float* w_out){
    int lo = 0, hi = nit;
    while(lo < hi){
        int mid = (lo + hi) >> 1;
        if(g_grid[mid] <= qt) lo = mid + 1; else hi = mid;
    }
    int gi = lo - 1;
    gi = max(0, min(gi, nit-2));
    float tl = g_grid[gi], tr = g_grid[gi+1];
    float den = tr - tl; if(den == 0.0f) den = 1.0f;
    *gi_out = gi;
    *w_out = (qt - tl) / den;
}

// ------------------------ k8: recon loss ------------------------------------
__global__ __launch_bounds__(128) void k_recon(const float* __restrict__ Wo1,
                                               const float* __restrict__ bo1,
                                               const float* __restrict__ Wo2,
                                               const float* __restrict__ bo2,
                                               const float* __restrict__ obs,
                                               const void* __restrict__ maskp,
                                               const int* __restrict__ tp,
                                               const int* __restrict__ seq_lens){
    extern __shared__ float sm[];
    float* wo1s = sm;                 // 64*128
    float* wo2s = wo1s + 64*128;      // 128*32
    float* bo1s = wo2s + 128*32;      // 128
    float* bo2s = bo1s + 128;         // 32
    float* zs   = bo2s + 32;          // 64*64
    float* h1s  = zs + TT*LATD;       // 128
    float* tw   = h1s + 128;          // 64
    int*   tgi  = (int*)(tw + TT);    // 64
    int tid = threadIdx.x, b = blockIdx.x;
    int mode = g_maskmode;
    for(int i = tid; i < 64*128; i += 128) wo1s[i] = Wo1[i];
    for(int i = tid; i < 128*32; i += 128) wo2s[i] = Wo2[i];
    bo1s[tid] = bo1[tid];
    if(tid < 32) bo2s[tid] = bo2[tid];
    int nit = g_niters;
    if(tid < TT){
        int v = tp[b*TT + tid];
        v = min(max(v, 0), TMAXV-1);
        float qt = g_qt[g_rank[v]];
        int gi; float w;
        interp_coeff(qt, nit, &gi, &w);
        tgi[tid] = gi; tw[tid] = w;
    }
    __syncthreads();
    for(int i = tid; i < TT*LATD; i += 128){
        int t = i >> 6, l = i & 63;
        int gi = tgi[t]; float w = tw[t];
        float zl = g_ys[((size_t)gi*BB + b)*LATD + l];
        float zr = g_ys[((size_t)(gi+1)*BB + b)*LATD + l];
        zs[i] = zl*(1.0f - w) + zr*w;
    }
    __syncthreads();
    int sl = seq_lens[b];
    if(sl > TT) sl = TT;
    double lsse = 0.0; float lnm = 0.0f;
    for(int t = 0; t < sl; t++){
        float acc = bo1s[tid];
        #pragma unroll 8
        for(int k = 0; k < 64; k++) acc = fmaf(zs[t*64+k], wo1s[k*128 + tid], acc);
        h1s[tid] = fmaxf(acc, 0.0f);
        __syncthreads();
        if(tid < NLL){
            float o = bo2s[tid];
            #pragma unroll 8
            for(int k = 0; k < 128; k++) o = fmaf(h1s[k], wo2s[k*32 + tid], o);
            float m = mread(maskp, (size_t)(b*TT + t)*NLL + tid, mode);
            float d = o - obs[(size_t)(b*TT + t)*NLL + tid];
            lsse += (double)(m*d*d);
            lnm  += m;
        }
        __syncthreads();
    }
    if(tid < 32){
        #pragma unroll
        for(int o = 16; o > 0; o >>= 1){
            lsse += __shfl_down_sync(0xffffffffu, lsse, o);
            lnm  += __shfl_down_sync(0xffffffffu, lnm,  o);
        }
        if(tid == 0){
            atomicAdd(&g_sse, lsse);
            atomicAdd(&g_nobs, (double)lnm);
        }
    }
}

// ------------------------ k9: z_eval + hazard -------------------------------
__global__ __launch_bounds__(128) void k_hazard(const float* __restrict__ Ws1,
                                                const float* __restrict__ bs1,
                                                const float* __restrict__ Ws2,
                                                const float* __restrict__ bs2,
                                                const float* __restrict__ age,
                                                const int* __restrict__ tp,
                                                const int* __restrict__ seq_lens,
                                                float* __restrict__ out){
    __shared__ float zev[DIN];    // z_eval (64) + age (1)
    __shared__ float hbuf[HIDD];
    int tid = threadIdx.x, b = blockIdx.x;
    int nit = g_niters;
    int sl = seq_lens[b];
    if(sl < 1) sl = 1; if(sl > TT) sl = TT;
    int v = tp[b*TT + sl - 1];
    v = min(max(v, 0), TMAXV-1);
    float qt = g_qt[g_rank[v]];
    int gi; float w;
    interp_coeff(qt, nit, &gi, &w);
    if(tid < LATD){
        float zl = g_ys[((size_t)gi*BB + b)*LATD + tid];
        float zr = g_ys[((size_t)(gi+1)*BB + b)*LATD + tid];
        float z = zl*(1.0f - w) + zr*w;
        zev[tid] = z;
        out[1026 + b*LATD + tid] = z;   // z_eval output
    }
    if(tid == 0) zev[LATD] = age[b];
    __syncthreads();
    float acc = bs1[tid];
    #pragma unroll 8
    for(int k = 0; k < DIN; k++) acc = fmaf(zev[k], Ws1[k*HIDD + tid], acc);
    hbuf[tid] = fmaxf(acc, 0.0f);
    __syncthreads();
    if(tid < 2){
        float o = bs2[tid];
        #pragma unroll 8
        for(int k = 0; k < HIDD; k++) o = fmaf(hbuf[k], Ws2[k*2 + tid], o);
        out[b*2 + tid] = o;             // log_hazard output
    }
}

// ------------------------ k10: write scalars --------------------------------
__global__ void k_final(float* __restrict__ out){
    if(threadIdx.x == 0){
        double n = g_nobs;
        out[1024] = (n > 0.0) ? (float)(g_sse / fmax(n, 1.0)) : 0.0f;   // recon
        out[1025] = (float)(-0.5 * g_kl / (double)BB);                   // kl
    }
}

// ------------------------ launch --------------------------------------------
extern "C" void kernel_launch(void* const* d_in, const int* in_sizes, int n_in,
                              void* d_out, int out_size){
    (void)in_sizes; (void)n_in; (void)out_size;
    const float* obs = (const float*)d_in[0];
    const float* age = (const float*)d_in[1];
    const float* eps = (const float*)d_in[2];
    const float* Wih = (const float*)d_in[3];
    const float* Whh = (const float*)d_in[4];
    const float* bih = (const float*)d_in[5];
    const float* bhh = (const float*)d_in[6];
    const float* Wmu = (const float*)d_in[7];
    const float* bmu = (const float*)d_in[8];
    const float* Wlv = (const float*)d_in[9];
    const float* blv = (const float*)d_in[10];
    const float* W1  = (const float*)d_in[11];
    const float* b1  = (const float*)d_in[12];
    const float* W2  = (const float*)d_in[13];
    const float* b2  = (const float*)d_in[14];
    const float* W3  = (const float*)d_in[15];
    const float* b3  = (const float*)d_in[16];
    const float* Wo1 = (const float*)d_in[17];
    const float* bo1 = (const float*)d_in[18];
    const float* Wo2 = (const float*)d_in[19];
    const float* bo2 = (const float*)d_in[20];
    const float* Ws1 = (const float*)d_in[21];
    const float* bs1 = (const float*)d_in[22];
    const float* Ws2 = (const float*)d_in[23];
    const float* bs2 = (const float*)d_in[24];
    const void*  msk = d_in[25];
    const int*   tp  = (const int*)d_in[26];
    const int*   seq = (const int*)d_in[27];
    float* out = (float*)d_out;

    const int GRU_SMEM = GRU_SMEM_BYTES;
    const int RK4_SMEM = RK4_SMEM_BYTES;
    const int REC_SMEM = (64*128 + 128*32 + 128 + 32 + TT*LATD + 128 + TT)*4
                         + TT*4;

    cudaFuncSetAttribute(k_gru,   cudaFuncAttributeMaxDynamicSharedMemorySize, GRU_SMEM);
    cudaFuncSetAttribute(k_rk4,   cudaFuncAttributeMaxDynamicSharedMemorySize, RK4_SMEM);
    cudaFuncSetAttribute(k_recon, cudaFuncAttributeMaxDynamicSharedMemorySize, REC_SMEM);

    k_zero  <<<9, 256>>>();
    k_detect<<<1, 256>>>(msk);
    k_mark  <<<(BB*TT + 255)/256, 256>>>(tp);
    k_build <<<1, 256>>>();
    k_gi    <<<BB*TT/GITILE, 384>>>(obs, msk, tp, Wih, bih);
    k_gru   <<<BB/4, 384, GRU_SMEM>>>(Whh, bhh);
    k_latent<<<BB, 64>>>(Wmu, bmu, Wlv, blv, eps);
    k_rk4   <<<BB/4, 128, RK4_SMEM>>>(W1, b1, W2, b2, W3, b3);
    k_recon <<<BB, 128, REC_SMEM>>>(Wo1, bo1, Wo2, bo2, obs, msk, tp, seq);
    k_hazard<<<BB, 128>>>(Ws1, bs1, Ws2, bs2, age, tp, seq, out);
    k_final <<<1, 32>>>(out);
}

// round 7
// speedup vs baseline: 1.7728x; 1.3026x over previous
#include <cuda_runtime.h>
#include <math.h>
#include <stdint.h>

#define BB 512
#define TT 64
#define NLL 32
#define LATD 64
#define HIDD 128
#define DIN 65
#define G3 384
#define TMAXV 2000
#define QPADV 2000
#define MAXG 160
#define SCALE_F 365.0f

// ------------------------ device scratch (static, no allocs) ----------------
__device__ float  g_GI[BB*TT*G3];
__device__ float  g_h[BB*HIDD];
__device__ float  g_z0[BB*LATD];
__device__ int    g_pres[TMAXV];
__device__ int    g_rank[TMAXV];
__device__ float  g_qt[QPADV];
__device__ float  g_grid[MAXG];
__device__ int    g_niters;
__device__ int    g_maskmode;
__device__ double g_sse, g_nobs, g_kl;
__device__ float  g_ys[(size_t)MAXG*BB*LATD];

// ------------------------ helpers -------------------------------------------
__device__ __forceinline__ float fsigm(float x){
    return __fdividef(1.0f, 1.0f + __expf(-x));
}
__device__ __forceinline__ float ftanh(float x){
    float e = __expf(-2.0f*fabsf(x));
    float r = __fdividef(1.0f - e, 1.0f + e);
    return __int_as_float(__float_as_int(r) | (__float_as_int(x) & 0x80000000));
}
__device__ __forceinline__ unsigned long long pk2f(float a, float b){
    unsigned long long r;
    asm("mov.b64 %0, {%1, %2};" : "=l"(r) : "f"(a), "f"(b));
    return r;
}
__device__ __forceinline__ unsigned long long ffma2(unsigned long long a,
                                                    unsigned long long b,
                                                    unsigned long long c){
    unsigned long long d;
    asm("fma.rn.f32x2 %0, %1, %2, %3;" : "=l"(d) : "l"(a), "l"(b), "l"(c));
    return d;
}
__device__ __forceinline__ float hadd2(unsigned long long v){
    float2 f;
    asm("mov.b64 {%0, %1}, %2;" : "=f"(f.x), "=f"(f.y) : "l"(v));
    return f.x + f.y;
}

__device__ __forceinline__ float mread(const void* m, size_t idx, int mode){
    if(mode==0) return ((const unsigned char*)m)[idx] ? 1.0f : 0.0f;
    if(mode==1) return ((const int*)m)[idx]           ? 1.0f : 0.0f;
    return ((const float*)m)[idx] != 0.0f ? 1.0f : 0.0f;
}

// ------------------------ k0: zero state ------------------------------------
__global__ void k_zero(){
    int i = blockIdx.x*blockDim.x + threadIdx.x;
    if(i < TMAXV) g_pres[i] = 0;
    if(i == 0){ g_sse = 0.0; g_nobs = 0.0; g_kl = 0.0; }
}

// ------------------------ k1: detect mask dtype -----------------------------
__global__ void k_detect(const void* m){
    __shared__ int flags[3]; // notF32, hasOne, isU8
    int tid = threadIdx.x;
    if(tid < 3) flags[tid] = 0;
    __syncthreads();
    const unsigned int* w = (const unsigned int*)m;
    int notf = 0, one = 0;
    for(int i = tid; i < 1024; i += 256){
        unsigned v = w[i];
        if(v == 0x3f800000u) one = 1; else if(v != 0u) notf = 1;
    }
    const unsigned char* c = (const unsigned char*)m;
    int u8 = 0;
    for(int i = tid; i < 4096; i += 256){ if((i & 3) && c[i]) u8 = 1; }
    if(notf) atomicOr(&flags[0], 1);
    if(one)  atomicOr(&flags[1], 1);
    if(u8)   atomicOr(&flags[2], 1);
    __syncthreads();
    if(tid == 0){
        if(!flags[0] && flags[1]) g_maskmode = 2;
        else g_maskmode = flags[2] ? 0 : 1;
    }
}

// ------------------------ k2: mark presence ---------------------------------
__global__ void k_mark(const int* __restrict__ tp){
    int i = blockIdx.x*blockDim.x + threadIdx.x;
    if(i < BB*TT){
        int v = tp[i];
        v = min(max(v, 0), TMAXV-1);
        g_pres[v] = 1;
    }
}

// ------------------------ k3: unique/rank/query/grid ------------------------
__global__ void k_build(){
    __shared__ int cnt[256];
    __shared__ int su[QPADV];
    __shared__ int sNU, sNit;
    int tid = threadIdx.x;
    int base = tid*8;
    int c = 0;
    for(int i = 0; i < 8; i++){ int v = base+i; if(v < TMAXV && g_pres[v]) c++; }
    cnt[tid] = c;
    __syncthreads();
    if(tid == 0){
        int run = 0;
        for(int i = 0; i < 256; i++){ int t = cnt[i]; cnt[i] = run; run += t; }
        sNU = run;
    }
    __syncthreads();
    int r = cnt[tid];
    for(int i = 0; i < 8; i++){
        int v = base+i;
        if(v < TMAXV){
            if(g_pres[v]){ g_rank[v] = r; su[r] = v; r++; }
            else g_rank[v] = 0;
        }
    }
    __syncthreads();
    int U = sNU;
    int mx = su[U-1];
    float t0f = (float)su[0]/SCALE_F;
    float t1f = (float)mx/SCALE_F;
    if(tid == 0){
        double nd = ceil(((double)t1f - (double)t0f)/0.05 + 1.0);
        int nit = (int)nd;
        if(nit < 2) nit = 2;
        if(nit > MAXG) nit = MAXG;
        g_niters = nit; sNit = nit;
    }
    __syncthreads();
    int nit = sNit;
    for(int q = tid; q < QPADV; q += 256){
        int v = (q < U) ? su[q] : mx;
        g_qt[q] = (float)v/SCALE_F;
    }
    double t0d = (double)t0f, t1d = (double)t1f;
    for(int i = tid; i < nit; i += 256){
        double gd = (double)i*0.05 + t0d;
        if(i == nit-1 && gd > t1d) gd = t1d;
        g_grid[i] = (float)gd;
    }
}

// ------------------------ k4: GI = x@Wih + bih ------------------------------
#define GITILE 32
__global__ __launch_bounds__(384) void k_gi(const float* __restrict__ obs,
                                            const void* __restrict__ maskp,
                                            const int* __restrict__ tp,
                                            const float* __restrict__ Wih,
                                            const float* __restrict__ bih){
    __shared__ float xs[GITILE][DIN];
    int tid = threadIdx.x;
    int mode = g_maskmode;
    int base = blockIdx.x * GITILE;
    for(int i = tid; i < GITILE*DIN; i += 384){
        int p = i / DIN, d = i - p*DIN;
        int bp = base + p;
        int t = bp & (TT-1);
        float v;
        if(d < NLL){
            float m = mread(maskp, (size_t)bp*NLL + d, mode);
            v = m * obs[(size_t)bp*NLL + d];
        } else if(d < 2*NLL){
            v = mread(maskp, (size_t)bp*NLL + (d-NLL), mode);
        } else {
            v = (t == 0) ? 0.0f : (float)(tp[bp] - tp[bp-1]);
        }
        xs[p][d] = v;
    }
    __syncthreads();
    int j = tid;
    float w[DIN];
    #pragma unroll
    for(int d = 0; d < DIN; d++) w[d] = Wih[d*G3 + j];
    float bj = bih[j];
    for(int p = 0; p < GITILE; p++){
        float acc = bj;
        #pragma unroll
        for(int d = 0; d < DIN; d++) acc = fmaf(xs[p][d], w[d], acc);
        g_GI[(size_t)(base+p)*G3 + j] = acc;
    }
}

// ------------------------ k5: GRU (k-packed f32x2, vectorized acts) ---------
#define GRU_SMEM_BYTES (64*384*8 + 384*16 + 384*16 + 4*128*4)
__global__ __launch_bounds__(384,1) void k_gru(const float* __restrict__ Whh,
                                               const float* __restrict__ bhh){
    extern __shared__ float sm[];
    unsigned long long* whhp = (unsigned long long*)sm;          // 64*384
    float4* gh4 = (float4*)(whhp + 64*384);                      // 384
    float4* gi4 = gh4 + G3;                                      // 384
    float*  hrow = (float*)(gi4 + G3);                           // 4*128
    int j  = threadIdx.x;
    int b0 = blockIdx.x * 4;
    for(int i = j; i < 64*G3; i += 384){
        int kp = i / G3, c = i - kp*G3;
        whhp[i] = pk2f(Whh[(2*kp)*G3 + c], Whh[(2*kp+1)*G3 + c]);
    }
    for(int i = j; i < 4*HIDD; i += 384) hrow[i] = 0.0f;
    float bj = bhh[j];
    const size_t rs = (size_t)TT*G3;
    const float* Gp0 = g_GI + (size_t)(b0+0)*rs;
    const float* Gp1 = g_GI + (size_t)(b0+1)*rs;
    const float* Gp2 = g_GI + (size_t)(b0+2)*rs;
    const float* Gp3 = g_GI + (size_t)(b0+3)*rs;
    const ulonglong2* hv2 = (const ulonglong2*)hrow;   // [r*32 + kk]
    __syncthreads();
    for(int s = 0; s < TT; s++){
        int t = TT-1-s;
        size_t off = (size_t)t*G3 + j;
        float gi0 = Gp0[off], gi1 = Gp1[off], gi2 = Gp2[off], gi3 = Gp3[off];
        unsigned long long a0 = pk2f(0.f,0.f), a1 = a0, a2 = a0, a3 = a0;
        #pragma unroll 8
        for(int kk = 0; kk < 32; kk++){
            unsigned long long wA = whhp[(2*kk)*G3 + j];
            unsigned long long wB = whhp[(2*kk+1)*G3 + j];
            ulonglong2 h0 = hv2[kk];
            ulonglong2 h1 = hv2[32 + kk];
            ulonglong2 h2 = hv2[64 + kk];
            ulonglong2 h3 = hv2[96 + kk];
            a0 = ffma2(h0.x, wA, a0); a0 = ffma2(h0.y, wB, a0);
            a1 = ffma2(h1.x, wA, a1); a1 = ffma2(h1.y, wB, a1);
            a2 = ffma2(h2.x, wA, a2); a2 = ffma2(h2.y, wB, a2);
            a3 = ffma2(h3.x, wA, a3); a3 = ffma2(h3.y, wB, a3);
        }
        gh4[j] = make_float4(hadd2(a0)+bj, hadd2(a1)+bj, hadd2(a2)+bj, hadd2(a3)+bj);
        gi4[j] = make_float4(gi0, gi1, gi2, gi3);
        __syncthreads();
        if(j < HIDD){
            float4 ir = gi4[j], iz = gi4[j+HIDD], in = gi4[j+2*HIDD];
            float4 hr = gh4[j], hz = gh4[j+HIDD], hn = gh4[j+2*HIDD];
            float h0 = hrow[j], h1 = hrow[HIDD+j], h2 = hrow[2*HIDD+j], h3 = hrow[3*HIDD+j];
            { float r = fsigm(ir.x+hr.x), z = fsigm(iz.x+hz.x);
              float n = ftanh(in.x + r*hn.x); hrow[j]        = (1.f-z)*n + z*h0; }
            { float r = fsigm(ir.y+hr.y), z = fsigm(iz.y+hz.y);
              float n = ftanh(in.y + r*hn.y); hrow[HIDD+j]   = (1.f-z)*n + z*h1; }
            { float r = fsigm(ir.z+hr.z), z = fsigm(iz.z+hz.z);
              float n = ftanh(in.z + r*hn.z); hrow[2*HIDD+j] = (1.f-z)*n + z*h2; }
            { float r = fsigm(ir.w+hr.w), z = fsigm(iz.w+hz.w);
              float n = ftanh(in.w + r*hn.w); hrow[3*HIDD+j] = (1.f-z)*n + z*h3; }
        }
        __syncthreads();
    }
    if(j < HIDD){
        g_h[(b0+0)*HIDD + j] = hrow[j];
        g_h[(b0+1)*HIDD + j] = hrow[HIDD+j];
        g_h[(b0+2)*HIDD + j] = hrow[2*HIDD+j];
        g_h[(b0+3)*HIDD + j] = hrow[3*HIDD+j];
    }
}

// ------------------------ k6: mu/logvar/z0/KL -------------------------------
__global__ __launch_bounds__(64) void k_latent(const float* __restrict__ Wmu,
                                               const float* __restrict__ bmu,
                                               const float* __restrict__ Wlv,
                                               const float* __restrict__ blv,
                                               const float* __restrict__ eps){
    __shared__ float hs[HIDD];
    __shared__ float red[LATD];
    int b = blockIdx.x, tid = threadIdx.x;
    hs[tid] = g_h[b*HIDD + tid];
    hs[tid+64] = g_h[b*HIDD + tid + 64];
    __syncthreads();
    float mu = bmu[tid], lv = blv[tid];
    #pragma unroll 8
    for(int k = 0; k < HIDD; k++){
        float h = hs[k];
        mu = fmaf(h, Wmu[k*LATD + tid], mu);
        lv = fmaf(h, Wlv[k*LATD + tid], lv);
    }
    g_z0[b*LATD + tid] = mu + eps[b*LATD + tid]*expf(0.5f*lv);
    red[tid] = 1.0f + lv - mu*mu - expf(lv);
    __syncthreads();
    if(tid == 0){
        float s = 0.f;
        for(int i = 0; i < LATD; i++) s += red[i];
        atomicAdd(&g_kl, (double)s);
    }
}

// ------------------------ k7: RK4 latent ODE (register weights, 256 thr) ----
// smem (floats): zrow 256 | a1 512 | a2 512 | red 1024 | ys 256 | kc 256 |
//                b1s 128 | b2s 128 | b3s 64 | gr 160  -> 3296 floats = 13184 B
#define RK4_SMEM_BYTES ((256 + 512 + 512 + 1024 + 256 + 256 + 128 + 128 + 64 + MAXG)*4)
__global__ __launch_bounds__(256,1) void k_rk4(const float* __restrict__ W1,
                                               const float* __restrict__ b1,
                                               const float* __restrict__ W2,
                                               const float* __restrict__ b2,
                                               const float* __restrict__ W3,
                                               const float* __restrict__ b3){
    extern __shared__ float sm[];
    float* zrow = sm;              // [r*64 + k]
    float* a1   = zrow + 256;      // [r*128 + k]
    float* a2   = a1 + 512;        // [r*128 + k]
    float* red  = a2 + 512;        // L1/L2: [h*512 + r*128 + j]; L3: [h*256 + r*64 + c3]
    float* ys_  = red + 1024;      // [r*64 + c3]
    float* kc   = ys_ + 256;       // [r*64 + c3]
    float* b1s  = kc + 256;
    float* b2s  = b1s + 128;
    float* b3s  = b2s + 128;
    float* gr   = b3s + 64;
    int tid = threadIdx.x;
    int j   = tid & 127;           // column, layers 1-2
    int p   = tid >> 7;            // k-half (warp-uniform)
    int c3  = tid & 63;            // column, layer 3
    int q   = tid >> 6;            // k-quarter / owned row (warp-uniform)

    // ---- weights into registers ----
    unsigned long long w1r[16];
    #pragma unroll
    for(int m = 0; m < 16; m++){
        int k0 = p*32 + 2*m;
        w1r[m] = pk2f(W1[k0*128 + j], W1[(k0+1)*128 + j]);
    }
    unsigned long long w2r[32];
    #pragma unroll
    for(int m = 0; m < 32; m++){
        int k0 = p*64 + 2*m;
        w2r[m] = pk2f(W2[k0*128 + j], W2[(k0+1)*128 + j]);
    }
    unsigned long long w3r[16];
    #pragma unroll
    for(int m = 0; m < 16; m++){
        int k0 = q*32 + 2*m;
        w3r[m] = pk2f(W3[k0*64 + c3], W3[(k0+1)*64 + c3]);
    }
    if(tid < 128){ b1s[tid] = b1[tid]; b2s[tid] = b2[tid]; }
    if(tid < 64)  b3s[tid] = b3[tid];
    int nit = g_niters;
    for(int i = tid; i < nit; i += 256) gr[i] = g_grid[i];
    int b0 = blockIdx.x * 4;
    if(tid < 64){
        int l = tid;
        #pragma unroll
        for(int r = 0; r < 4; r++){
            float z = g_z0[(b0+r)*LATD + l];
            zrow[r*64 + l] = z;
            ys_[r*64 + l] = z;
            g_ys[(size_t)(b0+r)*LATD + l] = z;
        }
    }
    __syncthreads();
    const ulonglong2* zv  = (const ulonglong2*)zrow;  // [r*16 + i2]
    const ulonglong2* a1v = (const ulonglong2*)a1;    // [r*32 + i2]
    const ulonglong2* a2v = (const ulonglong2*)a2;    // [r*32 + i2]
    for(int step = 0; step < nit-1; step++){
        float hs = gr[step+1] - gr[step];
        #pragma unroll
        for(int e = 0; e < 4; e++){
            // ============ layer 1: 64 -> 128, tanh ============
            {
                unsigned long long A0 = pk2f(0.f,0.f), A1 = A0, A2 = A0, A3 = A0;
                unsigned long long B0 = A0, B1 = A0, B2 = A0, B3 = A0;
                #pragma unroll
                for(int mm = 0; mm < 8; mm++){
                    unsigned long long wA = w1r[2*mm], wB = w1r[2*mm+1];
                    ulonglong2 z0 = zv[p*8 + mm];
                    ulonglong2 z1 = zv[16 + p*8 + mm];
                    ulonglong2 z2 = zv[32 + p*8 + mm];
                    ulonglong2 z3 = zv[48 + p*8 + mm];
                    A0 = ffma2(z0.x, wA, A0); B0 = ffma2(z0.y, wB, B0);
                    A1 = ffma2(z1.x, wA, A1); B1 = ffma2(z1.y, wB, B1);
                    A2 = ffma2(z2.x, wA, A2); B2 = ffma2(z2.y, wB, B2);
                    A3 = ffma2(z3.x, wA, A3); B3 = ffma2(z3.y, wB, B3);
                }
                red[p*512 + 0*128 + j] = hadd2(A0) + hadd2(B0);
                red[p*512 + 1*128 + j] = hadd2(A1) + hadd2(B1);
                red[p*512 + 2*128 + j] = hadd2(A2) + hadd2(B2);
                red[p*512 + 3*128 + j] = hadd2(A3) + hadd2(B3);
            }
            __syncthreads();
            {
                int r0 = 2*p, r1 = 2*p+1;
                float bb = b1s[j];
                float v0 = red[r0*128 + j] + red[512 + r0*128 + j] + bb;
                float v1 = red[r1*128 + j] + red[512 + r1*128 + j] + bb;
                a1[r0*128 + j] = ftanh(v0);
                a1[r1*128 + j] = ftanh(v1);
            }
            __syncthreads();
            // ============ layer 2: 128 -> 128, tanh ============
            {
                unsigned long long A0 = pk2f(0.f,0.f), A1 = A0, A2 = A0, A3 = A0;
                unsigned long long B0 = A0, B1 = A0, B2 = A0, B3 = A0;
                #pragma unroll
                for(int mm = 0; mm < 16; mm++){
                    unsigned long long wA = w2r[2*mm], wB = w2r[2*mm+1];
                    ulonglong2 x0 = a1v[p*16 + mm];
                    ulonglong2 x1 = a1v[32 + p*16 + mm];
                    ulonglong2 x2 = a1v[64 + p*16 + mm];
                    ulonglong2 x3 = a1v[96 + p*16 + mm];
                    A0 = ffma2(x0.x, wA, A0); B0 = ffma2(x0.y, wB, B0);
                    A1 = ffma2(x1.x, wA, A1); B1 = ffma2(x1.y, wB, B1);
                    A2 = ffma2(x2.x, wA, A2); B2 = ffma2(x2.y, wB, B2);
                    A3 = ffma2(x3.x, wA, A3); B3 = ffma2(x3.y, wB, B3);
                }
                red[p*512 + 0*128 + j] = hadd2(A0) + hadd2(B0);
                red[p*512 + 1*128 + j] = hadd2(A1) + hadd2(B1);
                red[p*512 + 2*128 + j] = hadd2(A2) + hadd2(B2);
                red[p*512 + 3*128 + j] = hadd2(A3) + hadd2(B3);
            }
            __syncthreads();
            {
                int r0 = 2*p, r1 = 2*p+1;
                float bb = b2s[j];
                float v0 = red[r0*128 + j] + red[512 + r0*128 + j] + bb;
                float v1 = red[r1*128 + j] + red[512 + r1*128 + j] + bb;
                a2[r0*128 + j] = ftanh(v0);
                a2[r1*128 + j] = ftanh(v1);
            }
            __syncthreads();
            // ============ layer 3: 128 -> 64 (k-quarter split) ============
            {
                unsigned long long A0 = pk2f(0.f,0.f), A1 = A0, A2 = A0, A3 = A0;
                unsigned long long B0 = A0, B1 = A0, B2 = A0, B3 = A0;
                #pragma unroll
                for(int mm = 0; mm < 8; mm++){
                    unsigned long long wA = w3r[2*mm], wB = w3r[2*mm+1];
                    ulonglong2 x0 = a2v[q*8 + mm];
                    ulonglong2 x1 = a2v[32 + q*8 + mm];
                    ulonglong2 x2 = a2v[64 + q*8 + mm];
                    ulonglong2 x3 = a2v[96 + q*8 + mm];
                    A0 = ffma2(x0.x, wA, A0); B0 = ffma2(x0.y, wB, B0);
                    A1 = ffma2(x1.x, wA, A1); B1 = ffma2(x1.y, wB, B1);
                    A2 = ffma2(x2.x, wA, A2); B2 = ffma2(x2.y, wB, B2);
                    A3 = ffma2(x3.x, wA, A3); B3 = ffma2(x3.y, wB, B3);
                }
                red[q*256 + 0*64 + c3] = hadd2(A0) + hadd2(B0);
                red[q*256 + 1*64 + c3] = hadd2(A1) + hadd2(B1);
                red[q*256 + 2*64 + c3] = hadd2(A2) + hadd2(B2);
                red[q*256 + 3*64 + c3] = hadd2(A3) + hadd2(B3);
            }
            __syncthreads();
            {
                // thread (c3, q) finalizes row r = q
                float f = red[0*256 + q*64 + c3] + red[1*256 + q*64 + c3]
                        + red[2*256 + q*64 + c3] + red[3*256 + q*64 + c3]
                        + b3s[c3];
                int idx = q*64 + c3;
                float yv = ys_[idx];
                if(e == 0){
                    kc[idx] = f;
                    zrow[idx] = yv + 0.5f*hs*f;
                } else if(e == 1){
                    kc[idx] += 2.0f*f;
                    zrow[idx] = yv + 0.5f*hs*f;
                } else if(e == 2){
                    kc[idx] += 2.0f*f;
                    zrow[idx] = yv + hs*f;
                } else {
                    float yn = yv + (hs/6.0f)*(kc[idx] + f);
                    ys_[idx] = yn;
                    zrow[idx] = yn;
                    g_ys[((size_t)(step+1)*BB + b0 + q)*LATD + c3] = yn;
                }
            }
            __syncthreads();
        }
    }
}

// ------------------------ interp helper -------------------------------------
__device__ __forceinline__ void interp_coeff(float qt, int nit, int* gi_out, float* w_out){
    int lo = 0, hi = nit;
    while(lo < hi){
        int mid = (lo + hi) >> 1;
        if(g_grid[mid] <= qt) lo = mid + 1; else hi = mid;
    }
    int gi = lo - 1;
    gi = max(0, min(gi, nit-2));
    float tl = g_grid[gi], tr = g_grid[gi+1];
    float den = tr - tl; if(den == 0.0f) den = 1.0f;
    *gi_out = gi;
    *w_out = (qt - tl) / den;
}

// ------------------------ k8: recon loss ------------------------------------
__global__ __launch_bounds__(128) void k_recon(const float* __restrict__ Wo1,
                                               const float* __restrict__ bo1,
                                               const float* __restrict__ Wo2,
                                               const float* __restrict__ bo2,
                                               const float* __restrict__ obs,
                                               const void* __restrict__ maskp,
                                               const int* __restrict__ tp,
                                               const int* __restrict__ seq_lens){
    extern __shared__ float sm[];
    float* wo1s = sm;                 // 64*128
    float* wo2s = wo1s + 64*128;      // 128*32
    float* bo1s = wo2s + 128*32;      // 128
    float* bo2s = bo1s + 128;         // 32
    float* zs   = bo2s + 32;          // 64*64
    float* h1s  = zs + TT*LATD;       // 128
    float* tw   = h1s + 128;          // 64
    int*   tgi  = (int*)(tw + TT);    // 64
    int tid = threadIdx.x, b = blockIdx.x;
    int mode = g_maskmode;
    for(int i = tid; i < 64*128; i += 128) wo1s[i] = Wo1[i];
    for(int i = tid; i < 128*32; i += 128) wo2s[i] = Wo2[i];
    bo1s[tid] = bo1[tid];
    if(tid < 32) bo2s[tid] = bo2[tid];
    int nit = g_niters;
    if(tid < TT){
        int v = tp[b*TT + tid];
        v = min(max(v, 0), TMAXV-1);
        float qt = g_qt[g_rank[v]];
        int gi; float w;
        interp_coeff(qt, nit, &gi, &w);
        tgi[tid] = gi; tw[tid] = w;
    }
    __syncthreads();
    for(int i = tid; i < TT*LATD; i += 128){
        int t = i >> 6, l = i & 63;
        int gi = tgi[t]; float w = tw[t];
        float zl = g_ys[((size_t)gi*BB + b)*LATD + l];
        float zr = g_ys[((size_t)(gi+1)*BB + b)*LATD + l];
        zs[i] = zl*(1.0f - w) + zr*w;
    }
    __syncthreads();
    int sl = seq_lens[b];
    if(sl > TT) sl = TT;
    double lsse = 0.0; float lnm = 0.0f;
    for(int t = 0; t < sl; t++){
        float acc = bo1s[tid];
        #pragma unroll 8
        for(int k = 0; k < 64; k++) acc = fmaf(zs[t*64+k], wo1s[k*128 + tid], acc);
        h1s[tid] = fmaxf(acc, 0.0f);
        __syncthreads();
        if(tid < NLL){
            float o = bo2s[tid];
            #pragma unroll 8
            for(int k = 0; k < 128; k++) o = fmaf(h1s[k], wo2s[k*32 + tid], o);
            float m = mread(maskp, (size_t)(b*TT + t)*NLL + tid, mode);
            float d = o - obs[(size_t)(b*TT + t)*NLL + tid];
            lsse += (double)(m*d*d);
            lnm  += m;
        }
        __syncthreads();
    }
    if(tid < 32){
        #pragma unroll
        for(int o = 16; o > 0; o >>= 1){
            lsse += __shfl_down_sync(0xffffffffu, lsse, o);
            lnm  += __shfl_down_sync(0xffffffffu, lnm,  o);
        }
        if(tid == 0){
            atomicAdd(&g_sse, lsse);
            atomicAdd(&g_nobs, (double)lnm);
        }
    }
}

// ------------------------ k9: z_eval + hazard -------------------------------
__global__ __launch_bounds__(128) void k_hazard(const float* __restrict__ Ws1,
                                                const float* __restrict__ bs1,
                                                const float* __restrict__ Ws2,
                                                const float* __restrict__ bs2,
                                                const float* __restrict__ age,
                                                const int* __restrict__ tp,
                                                const int* __restrict__ seq_lens,
                                                float* __restrict__ out){
    __shared__ float zev[DIN];    // z_eval (64) + age (1)
    __shared__ float hbuf[HIDD];
    int tid = threadIdx.x, b = blockIdx.x;
    int nit = g_niters;
    int sl = seq_lens[b];
    if(sl < 1) sl = 1; if(sl > TT) sl = TT;
    int v = tp[b*TT + sl - 1];
    v = min(max(v, 0), TMAXV-1);
    float qt = g_qt[g_rank[v]];
    int gi; float w;
    interp_coeff(qt, nit, &gi, &w);
    if(tid < LATD){
        float zl = g_ys[((size_t)gi*BB + b)*LATD + tid];
        float zr = g_ys[((size_t)(gi+1)*BB + b)*LATD + tid];
        float z = zl*(1.0f - w) + zr*w;
        zev[tid] = z;
        out[1026 + b*LATD + tid] = z;   // z_eval output
    }
    if(tid == 0) zev[LATD] = age[b];
    __syncthreads();
    float acc = bs1[tid];
    #pragma unroll 8
    for(int k = 0; k < DIN; k++) acc = fmaf(zev[k], Ws1[k*HIDD + tid], acc);
    hbuf[tid] = fmaxf(acc, 0.0f);
    __syncthreads();
    if(tid < 2){
        float o = bs2[tid];
        #pragma unroll 8
        for(int k = 0; k < HIDD; k++) o = fmaf(hbuf[k], Ws2[k*2 + tid], o);
        out[b*2 + tid] = o;             // log_hazard output
    }
}

// ------------------------ k10: write scalars --------------------------------
__global__ void k_final(float* __restrict__ out){
    if(threadIdx.x == 0){
        double n = g_nobs;
        out[1024] = (n > 0.0) ? (float)(g_sse / fmax(n, 1.0)) : 0.0f;   // recon
        out[1025] = (float)(-0.5 * g_kl / (double)BB);                   // kl
    }
}

// ------------------------ launch --------------------------------------------
extern "C" void kernel_launch(void* const* d_in, const int* in_sizes, int n_in,
                              void* d_out, int out_size){
    (void)in_sizes; (void)n_in; (void)out_size;
    const float* obs = (const float*)d_in[0];
    const float* age = (const float*)d_in[1];
    const float* eps = (const float*)d_in[2];
    const float* Wih = (const float*)d_in[3];
    const float* Whh = (const float*)d_in[4];
    const float* bih = (const float*)d_in[5];
    const float* bhh = (const float*)d_in[6];
    const float* Wmu = (const float*)d_in[7];
    const float* bmu = (const float*)d_in[8];
    const float* Wlv = (const float*)d_in[9];
    const float* blv = (const float*)d_in[10];
    const float* W1  = (const float*)d_in[11];
    const float* b1  = (const float*)d_in[12];
    const float* W2  = (const float*)d_in[13];
    const float* b2  = (const float*)d_in[14];
    const float* W3  = (const float*)d_in[15];
    const float* b3  = (const float*)d_in[16];
    const float* Wo1 = (const float*)d_in[17];
    const float* bo1 = (const float*)d_in[18];
    const float* Wo2 = (const float*)d_in[19];
    const float* bo2 = (const float*)d_in[20];
    const float* Ws1 = (const float*)d_in[21];
    const float* bs1 = (const float*)d_in[22];
    const float* Ws2 = (const float*)d_in[23];
    const float* bs2 = (const float*)d_in[24];
    const void*  msk = d_in[25];
    const int*   tp  = (const int*)d_in[26];
    const int*   seq = (const int*)d_in[27];
    float* out = (float*)d_out;

    const int GRU_SMEM = GRU_SMEM_BYTES;
    const int RK4_SMEM = RK4_SMEM_BYTES;
    const int REC_SMEM = (64*128 + 128*32 + 128 + 32 + TT*LATD + 128 + TT)*4
                         + TT*4;

    cudaFuncSetAttribute(k_gru,   cudaFuncAttributeMaxDynamicSharedMemorySize, GRU_SMEM);
    cudaFuncSetAttribute(k_rk4,   cudaFuncAttributeMaxDynamicSharedMemorySize, RK4_SMEM);
    cudaFuncSetAttribute(k_recon, cudaFuncAttributeMaxDynamicSharedMemorySize, REC_SMEM);

    k_zero  <<<9, 256>>>();
    k_detect<<<1, 256>>>(msk);
    k_mark  <<<(BB*TT + 255)/256, 256>>>(tp);
    k_build <<<1, 256>>>();
    k_gi    <<<BB*TT/GITILE, 384>>>(obs, msk, tp, Wih, bih);
    k_gru   <<<BB/4, 384, GRU_SMEM>>>(Whh, bhh);
    k_latent<<<BB, 64>>>(Wmu, bmu, Wlv, blv, eps);
    k_rk4   <<<BB/4, 256, RK4_SMEM>>>(W1, b1, W2, b2, W3, b3);
    k_recon <<<BB, 128, REC_SMEM>>>(Wo1, bo1, Wo2, bo2, obs, msk, tp, seq);
    k_hazard<<<BB, 128>>>(Ws1, bs1, Ws2, bs2, age, tp, seq, out);
    k_final <<<1, 32>>>(out);
}

// round 9
// speedup vs baseline: 1.7749x; 1.0012x over previous
#include <cuda_runtime.h>
#include <math.h>
#include <stdint.h>

#define BB 512
#define TT 64
#define NLL 32
#define LATD 64
#define HIDD 128
#define DIN 65
#define G3 384
#define TMAXV 2000
#define QPADV 2000
#define MAXG 160
#define SCALE_F 365.0f

// ------------------------ device scratch (static, no allocs) ----------------
__device__ float  g_GI[BB*TT*G3];
__device__ float  g_h[BB*HIDD];
__device__ float  g_z0[BB*LATD];
__device__ int    g_pres[TMAXV];
__device__ int    g_rank[TMAXV];
__device__ float  g_qt[QPADV];
__device__ float  g_grid[MAXG];
__device__ int    g_niters;
__device__ int    g_maskmode;
__device__ double g_sse, g_nobs, g_kl;
__device__ float  g_ys[(size_t)MAXG*BB*LATD];

// ------------------------ helpers -------------------------------------------
__device__ __forceinline__ float fsigm(float x){
    return __fdividef(1.0f, 1.0f + __expf(-x));
}
__device__ __forceinline__ float ftanh(float x){
    float e = __expf(-2.0f*fabsf(x));
    float r = __fdividef(1.0f - e, 1.0f + e);
    return __int_as_float(__float_as_int(r) | (__float_as_int(x) & 0x80000000));
}
__device__ __forceinline__ unsigned long long pk2f(float a, float b){
    unsigned long long r;
    asm("mov.b64 %0, {%1, %2};" : "=l"(r) : "f"(a), "f"(b));
    return r;
}
__device__ __forceinline__ unsigned long long ffma2(unsigned long long a,
                                                    unsigned long long b,
                                                    unsigned long long c){
    unsigned long long d;
    asm("fma.rn.f32x2 %0, %1, %2, %3;" : "=l"(d) : "l"(a), "l"(b), "l"(c));
    return d;
}
__device__ __forceinline__ float hadd2(unsigned long long v){
    float2 f;
    asm("mov.b64 {%0, %1}, %2;" : "=f"(f.x), "=f"(f.y) : "l"(v));
    return f.x + f.y;
}
// swizzle a float index within a row: permute 16B chunks, c -> c ^ ((c>>3)&3)
__device__ __forceinline__ int swf(int k){
    int c = k >> 2;
    int t = (c >> 3) & 3;
    return (((c ^ t) << 2) | (k & 3));
}

__device__ __forceinline__ float mread(const void* m, size_t idx, int mode){
    if(mode==0) return ((const unsigned char*)m)[idx] ? 1.0f : 0.0f;
    if(mode==1) return ((const int*)m)[idx]           ? 1.0f : 0.0f;
    return ((const float*)m)[idx] != 0.0f ? 1.0f : 0.0f;
}

// ------------------------ k0: zero + detect (fused) --------------------------
__global__ void k_zerodetect(const void* m){
    if(blockIdx.x < 8){
        int i = blockIdx.x*256 + threadIdx.x;
        if(i < TMAXV) g_pres[i] = 0;
        if(blockIdx.x == 0 && threadIdx.x == 0){ g_sse = 0.0; g_nobs = 0.0; g_kl = 0.0; }
        return;
    }
    __shared__ int flags[3];
    int tid = threadIdx.x;
    if(tid < 3) flags[tid] = 0;
    __syncthreads();
    const unsigned int* w = (const unsigned int*)m;
    int notf = 0, one = 0;
    for(int i = tid; i < 1024; i += 256){
        unsigned v = w[i];
        if(v == 0x3f800000u) one = 1; else if(v != 0u) notf = 1;
    }
    const unsigned char* c = (const unsigned char*)m;
    int u8 = 0;
    for(int i = tid; i < 4096; i += 256){ if((i & 3) && c[i]) u8 = 1; }
    if(notf) atomicOr(&flags[0], 1);
    if(one)  atomicOr(&flags[1], 1);
    if(u8)   atomicOr(&flags[2], 1);
    __syncthreads();
    if(tid == 0){
        if(!flags[0] && flags[1]) g_maskmode = 2;
        else g_maskmode = flags[2] ? 0 : 1;
    }
}

// ------------------------ k2: mark presence ---------------------------------
__global__ void k_mark(const int* __restrict__ tp){
    int i = blockIdx.x*blockDim.x + threadIdx.x;
    if(i < BB*TT){
        int v = tp[i];
        v = min(max(v, 0), TMAXV-1);
        g_pres[v] = 1;
    }
}

// ------------------------ k3: unique/rank/query/grid ------------------------
__global__ void k_build(){
    __shared__ int cnt[256];
    __shared__ int su[QPADV];
    __shared__ int sNU, sNit;
    int tid = threadIdx.x;
    int base = tid*8;
    int c = 0;
    for(int i = 0; i < 8; i++){ int v = base+i; if(v < TMAXV && g_pres[v]) c++; }
    cnt[tid] = c;
    __syncthreads();
    if(tid == 0){
        int run = 0;
        for(int i = 0; i < 256; i++){ int t = cnt[i]; cnt[i] = run; run += t; }
        sNU = run;
    }
    __syncthreads();
    int r = cnt[tid];
    for(int i = 0; i < 8; i++){
        int v = base+i;
        if(v < TMAXV){
            if(g_pres[v]){ g_rank[v] = r; su[r] = v; r++; }
            else g_rank[v] = 0;
        }
    }
    __syncthreads();
    int U = sNU;
    int mx = su[U-1];
    float t0f = (float)su[0]/SCALE_F;
    float t1f = (float)mx/SCALE_F;
    if(tid == 0){
        double nd = ceil(((double)t1f - (double)t0f)/0.05 + 1.0);
        int nit = (int)nd;
        if(nit < 2) nit = 2;
        if(nit > MAXG) nit = MAXG;
        g_niters = nit; sNit = nit;
    }
    __syncthreads();
    int nit = sNit;
    for(int q = tid; q < QPADV; q += 256){
        int v = (q < U) ? su[q] : mx;
        g_qt[q] = (float)v/SCALE_F;
    }
    double t0d = (double)t0f, t1d = (double)t1f;
    for(int i = tid; i < nit; i += 256){
        double gd = (double)i*0.05 + t0d;
        if(i == nit-1 && gd > t1d) gd = t1d;
        g_grid[i] = (float)gd;
    }
}

// ------------------------ k4: GI = x@Wih + bih ------------------------------
#define GITILE 32
__global__ __launch_bounds__(384) void k_gi(const float* __restrict__ obs,
                                            const void* __restrict__ maskp,
                                            const int* __restrict__ tp,
                                            const float* __restrict__ Wih,
                                            const float* __restrict__ bih){
    __shared__ float xs[GITILE][DIN];
    int tid = threadIdx.x;
    int mode = g_maskmode;
    int base = blockIdx.x * GITILE;
    for(int i = tid; i < GITILE*DIN; i += 384){
        int p = i / DIN, d = i - p*DIN;
        int bp = base + p;
        int t = bp & (TT-1);
        float v;
        if(d < NLL){
            float m = mread(maskp, (size_t)bp*NLL + d, mode);
            v = m * obs[(size_t)bp*NLL + d];
        } else if(d < 2*NLL){
            v = mread(maskp, (size_t)bp*NLL + (d-NLL), mode);
        } else {
            v = (t == 0) ? 0.0f : (float)(tp[bp] - tp[bp-1]);
        }
        xs[p][d] = v;
    }
    __syncthreads();
    int j = tid;
    float w[DIN];
    #pragma unroll
    for(int d = 0; d < DIN; d++) w[d] = Wih[d*G3 + j];
    float bj = bih[j];
    for(int p = 0; p < GITILE; p++){
        float acc = bj;
        #pragma unroll
        for(int d = 0; d < DIN; d++) acc = fmaf(xs[p][d], w[d], acc);
        g_GI[(size_t)(base+p)*G3 + j] = acc;
    }
}

// ------------------------ k5: GRU (k-packed f32x2, vectorized acts) ---------
#define GRU_SMEM_BYTES (64*384*8 + 384*16 + 384*16 + 4*128*4)
__global__ __launch_bounds__(384,1) void k_gru(const float* __restrict__ Whh,
                                               const float* __restrict__ bhh){
    extern __shared__ float sm[];
    unsigned long long* whhp = (unsigned long long*)sm;          // 64*384
    float4* gh4 = (float4*)(whhp + 64*384);                      // 384
    float4* gi4 = gh4 + G3;                                      // 384
    float*  hrow = (float*)(gi4 + G3);                           // 4*128
    int j  = threadIdx.x;
    int b0 = blockIdx.x * 4;
    for(int i = j; i < 64*G3; i += 384){
        int kp = i / G3, c = i - kp*G3;
        whhp[i] = pk2f(Whh[(2*kp)*G3 + c], Whh[(2*kp+1)*G3 + c]);
    }
    for(int i = j; i < 4*HIDD; i += 384) hrow[i] = 0.0f;
    float bj = bhh[j];
    const size_t rs = (size_t)TT*G3;
    const float* Gp0 = g_GI + (size_t)(b0+0)*rs;
    const float* Gp1 = g_GI + (size_t)(b0+1)*rs;
    const float* Gp2 = g_GI + (size_t)(b0+2)*rs;
    const float* Gp3 = g_GI + (size_t)(b0+3)*rs;
    const ulonglong2* hv2 = (const ulonglong2*)hrow;   // [r*32 + kk]
    __syncthreads();
    for(int s = 0; s < TT; s++){
        int t = TT-1-s;
        size_t off = (size_t)t*G3 + j;
        float gi0 = Gp0[off], gi1 = Gp1[off], gi2 = Gp2[off], gi3 = Gp3[off];
        unsigned long long a0 = pk2f(0.f,0.f), a1 = a0, a2 = a0, a3 = a0;
        #pragma unroll 8
        for(int kk = 0; kk < 32; kk++){
            unsigned long long wA = whhp[(2*kk)*G3 + j];
            unsigned long long wB = whhp[(2*kk+1)*G3 + j];
            ulonglong2 h0 = hv2[kk];
            ulonglong2 h1 = hv2[32 + kk];
            ulonglong2 h2 = hv2[64 + kk];
            ulonglong2 h3 = hv2[96 + kk];
            a0 = ffma2(h0.x, wA, a0); a0 = ffma2(h0.y, wB, a0);
            a1 = ffma2(h1.x, wA, a1); a1 = ffma2(h1.y, wB, a1);
            a2 = ffma2(h2.x, wA, a2); a2 = ffma2(h2.y, wB, a2);
            a3 = ffma2(h3.x, wA, a3); a3 = ffma2(h3.y, wB, a3);
        }
        gh4[j] = make_float4(hadd2(a0)+bj, hadd2(a1)+bj, hadd2(a2)+bj, hadd2(a3)+bj);
        gi4[j] = make_float4(gi0, gi1, gi2, gi3);
        __syncthreads();
        if(j < HIDD){
            float4 ir = gi4[j], iz = gi4[j+HIDD], in = gi4[j+2*HIDD];
            float4 hr = gh4[j], hz = gh4[j+HIDD], hn = gh4[j+2*HIDD];
            float h0 = hrow[j], h1 = hrow[HIDD+j], h2 = hrow[2*HIDD+j], h3 = hrow[3*HIDD+j];
            { float r = fsigm(ir.x+hr.x), z = fsigm(iz.x+hz.x);
              float n = ftanh(in.x + r*hn.x); hrow[j]        = (1.f-z)*n + z*h0; }
            { float r = fsigm(ir.y+hr.y), z = fsigm(iz.y+hz.y);
              float n = ftanh(in.y + r*hn.y); hrow[HIDD+j]   = (1.f-z)*n + z*h1; }
            { float r = fsigm(ir.z+hr.z), z = fsigm(iz.z+hz.z);
              float n = ftanh(in.z + r*hn.z); hrow[2*HIDD+j] = (1.f-z)*n + z*h2; }
            { float r = fsigm(ir.w+hr.w), z = fsigm(iz.w+hz.w);
              float n = ftanh(in.w + r*hn.w); hrow[3*HIDD+j] = (1.f-z)*n + z*h3; }
        }
        __syncthreads();
    }
    if(j < HIDD){
        g_h[(b0+0)*HIDD + j] = hrow[j];
        g_h[(b0+1)*HIDD + j] = hrow[HIDD+j];
        g_h[(b0+2)*HIDD + j] = hrow[2*HIDD+j];
        g_h[(b0+3)*HIDD + j] = hrow[3*HIDD+j];
    }
}

// ------------------------ k6: mu/logvar/z0/KL -------------------------------
__global__ __launch_bounds__(64) void k_latent(const float* __restrict__ Wmu,
                                               const float* __restrict__ bmu,
                                               const float* __restrict__ Wlv,
                                               const float* __restrict__ blv,
                                               const float* __restrict__ eps){
    __shared__ float hs[HIDD];
    __shared__ float red[LATD];
    int b = blockIdx.x, tid = threadIdx.x;
    hs[tid] = g_h[b*HIDD + tid];
    hs[tid+64] = g_h[b*HIDD + tid + 64];
    __syncthreads();
    float mu = bmu[tid], lv = blv[tid];
    #pragma unroll 8
    for(int k = 0; k < HIDD; k++){
        float h = hs[k];
        mu = fmaf(h, Wmu[k*LATD + tid], mu);
        lv = fmaf(h, Wlv[k*LATD + tid], lv);
    }
    g_z0[b*LATD + tid] = mu + eps[b*LATD + tid]*expf(0.5f*lv);
    red[tid] = 1.0f + lv - mu*mu - expf(lv);
    __syncthreads();
    if(tid == 0){
        float s = 0.f;
        for(int i = 0; i < LATD; i++) s += red[i];
        atomicAdd(&g_kl, (double)s);
    }
}

// ------------------------ k7: RK4 (lane-split k + shuffle reduce) -----------
// smem (floats): zrow 256 | a1 512 | a2 512 | ys 256 | kc 256 |
//                b1s 128 | b2s 128 | b3s 64 | gr MAXG
#define RK4_SMEM_BYTES ((256 + 512 + 512 + 256 + 256 + 128 + 128 + 64 + MAXG)*4)
__global__ __launch_bounds__(256,1) void k_rk4(const float* __restrict__ W1,
                                               const float* __restrict__ b1,
                                               const float* __restrict__ W2,
                                               const float* __restrict__ b2,
                                               const float* __restrict__ W3,
                                               const float* __restrict__ b3){
    extern __shared__ float sm[];
    float* zrow = sm;              // [r*64 + swf(k)]
    float* a1   = zrow + 256;      // [r*128 + swf(k)]
    float* a2   = a1 + 512;        // [r*128 + swf(k)]
    float* ys_  = a2 + 512;        // [r*64 + c3] (thread-private slots)
    float* kc   = ys_ + 256;       // [r*64 + c3]
    float* b1s  = kc + 256;
    float* b2s  = b1s + 128;
    float* b3s  = b2s + 128;
    float* gr   = b3s + 64;
    int tid = threadIdx.x;
    int wq = tid >> 5, l = tid & 31;
    int j  = wq*16 + (l & 15);     // column, layers 1-2
    int p  = l >> 4;               // k-half (lane-varying)
    int c3 = wq*8 + (l & 7);       // column, layer 3
    int q  = l >> 3;               // k-quarter / owned row (lane-varying)
    int jz  = swf(j);              // swizzled store column for a1/a2
    int c3z = swf(c3);             // swizzled store column for zrow

    // ---- weights into registers ----
    unsigned long long w1r[16];
    #pragma unroll
    for(int m = 0; m < 16; m++){
        int k0 = p*32 + 2*m;
        w1r[m] = pk2f(W1[k0*128 + j], W1[(k0+1)*128 + j]);
    }
    unsigned long long w2r[32];
    #pragma unroll
    for(int m = 0; m < 32; m++){
        int k0 = p*64 + 2*m;
        w2r[m] = pk2f(W2[k0*128 + j], W2[(k0+1)*128 + j]);
    }
    unsigned long long w3r[16];
    #pragma unroll
    for(int m = 0; m < 16; m++){
        int k0 = q*32 + 2*m;
        w3r[m] = pk2f(W3[k0*64 + c3], W3[(k0+1)*64 + c3]);
    }
    if(tid < 128){ b1s[tid] = b1[tid]; b2s[tid] = b2[tid]; }
    if(tid < 64)  b3s[tid] = b3[tid];
    int nit = g_niters;
    for(int i = tid; i < nit; i += 256) gr[i] = g_grid[i];
    int b0 = blockIdx.x * 4;
    if(tid < 64){
        int lz = swf(tid);
        #pragma unroll
        for(int r = 0; r < 4; r++){
            float z = g_z0[(b0+r)*LATD + tid];
            zrow[r*64 + lz] = z;
            ys_[r*64 + tid] = z;
            g_ys[(size_t)(b0+r)*LATD + tid] = z;
        }
    }
    __syncthreads();
    const ulonglong2* zv  = (const ulonglong2*)zrow;  // [r*16 + sc]
    const ulonglong2* a1v = (const ulonglong2*)a1;    // [r*32 + sc]
    const ulonglong2* a2v = (const ulonglong2*)a2;    // [r*32 + sc]
    for(int step = 0; step < nit-1; step++){
        float hs = gr[step+1] - gr[step];
        #pragma unroll
        for(int e = 0; e < 4; e++){
            // ============ layer 1: 64 -> 128, tanh ============
            {
                unsigned long long A0 = pk2f(0.f,0.f), A1 = A0, A2 = A0, A3 = A0;
                unsigned long long B0 = A0, B1 = A0, B2 = A0, B3 = A0;
                #pragma unroll
                for(int mm = 0; mm < 8; mm++){
                    int sc = p*8 + (mm ^ p);
                    unsigned long long wA = w1r[2*mm], wB = w1r[2*mm+1];
                    ulonglong2 z0 = zv[sc];
                    ulonglong2 z1 = zv[16 + sc];
                    ulonglong2 z2 = zv[32 + sc];
                    ulonglong2 z3 = zv[48 + sc];
                    A0 = ffma2(z0.x, wA, A0); B0 = ffma2(z0.y, wB, B0);
                    A1 = ffma2(z1.x, wA, A1); B1 = ffma2(z1.y, wB, B1);
                    A2 = ffma2(z2.x, wA, A2); B2 = ffma2(z2.y, wB, B2);
                    A3 = ffma2(z3.x, wA, A3); B3 = ffma2(z3.y, wB, B3);
                }
                // NOTE: acts consumed per swizzled chunk match the k-range of
                // w1r because position sw(c) stores chunk c (writers swizzle).
                float s0 = hadd2(A0) + hadd2(B0);
                float s1 = hadd2(A1) + hadd2(B1);
                float s2 = hadd2(A2) + hadd2(B2);
                float s3 = hadd2(A3) + hadd2(B3);
                s0 += __shfl_xor_sync(0xffffffffu, s0, 16);
                s1 += __shfl_xor_sync(0xffffffffu, s1, 16);
                s2 += __shfl_xor_sync(0xffffffffu, s2, 16);
                s3 += __shfl_xor_sync(0xffffffffu, s3, 16);
                float bb = b1s[j];
                float u0 = p ? s2 : s0;
                float u1 = p ? s3 : s1;
                a1[(2*p)*128   + jz] = ftanh(u0 + bb);
                a1[(2*p+1)*128 + jz] = ftanh(u1 + bb);
            }
            __syncthreads();
            // ============ layer 2: 128 -> 128, tanh ============
            {
                unsigned long long A0 = pk2f(0.f,0.f), A1 = A0, A2 = A0, A3 = A0;
                unsigned long long B0 = A0, B1 = A0, B2 = A0, B3 = A0;
                #pragma unroll
                for(int mm = 0; mm < 16; mm++){
                    int cc = p*16 + mm;
                    int sc = cc ^ ((cc >> 3) & 3);
                    unsigned long long wA = w2r[2*mm], wB = w2r[2*mm+1];
                    ulonglong2 x0 = a1v[sc];
                    ulonglong2 x1 = a1v[32 + sc];
                    ulonglong2 x2 = a1v[64 + sc];
                    ulonglong2 x3 = a1v[96 + sc];
                    A0 = ffma2(x0.x, wA, A0); B0 = ffma2(x0.y, wB, B0);
                    A1 = ffma2(x1.x, wA, A1); B1 = ffma2(x1.y, wB, B1);
                    A2 = ffma2(x2.x, wA, A2); B2 = ffma2(x2.y, wB, B2);
                    A3 = ffma2(x3.x, wA, A3); B3 = ffma2(x3.y, wB, B3);
                }
                float s0 = hadd2(A0) + hadd2(B0);
                float s1 = hadd2(A1) + hadd2(B1);
                float s2 = hadd2(A2) + hadd2(B2);
                float s3 = hadd2(A3) + hadd2(B3);
                s0 += __shfl_xor_sync(0xffffffffu, s0, 16);
                s1 += __shfl_xor_sync(0xffffffffu, s1, 16);
                s2 += __shfl_xor_sync(0xffffffffu, s2, 16);
                s3 += __shfl_xor_sync(0xffffffffu, s3, 16);
                float bb = b2s[j];
                float u0 = p ? s2 : s0;
                float u1 = p ? s3 : s1;
                a2[(2*p)*128   + jz] = ftanh(u0 + bb);
                a2[(2*p+1)*128 + jz] = ftanh(u1 + bb);
            }
            __syncthreads();
            // ============ layer 3: 128 -> 64 (k-quarter in lanes) ============
            {
                unsigned long long A0 = pk2f(0.f,0.f), A1 = A0, A2 = A0, A3 = A0;
                unsigned long long B0 = A0, B1 = A0, B2 = A0, B3 = A0;
                #pragma unroll
                for(int mm = 0; mm < 8; mm++){
                    int sc = q*8 + (mm ^ q);
                    unsigned long long wA = w3r[2*mm], wB = w3r[2*mm+1];
                    ulonglong2 x0 = a2v[sc];
                    ulonglong2 x1 = a2v[32 + sc];
                    ulonglong2 x2 = a2v[64 + sc];
                    ulonglong2 x3 = a2v[96 + sc];
                    A0 = ffma2(x0.x, wA, A0); B0 = ffma2(x0.y, wB, B0);
                    A1 = ffma2(x1.x, wA, A1); B1 = ffma2(x1.y, wB, B1);
                    A2 = ffma2(x2.x, wA, A2); B2 = ffma2(x2.y, wB, B2);
                    A3 = ffma2(x3.x, wA, A3); B3 = ffma2(x3.y, wB, B3);
                }
                float s0 = hadd2(A0) + hadd2(B0);
                float s1 = hadd2(A1) + hadd2(B1);
                float s2 = hadd2(A2) + hadd2(B2);
                float s3 = hadd2(A3) + hadd2(B3);
                s0 += __shfl_xor_sync(0xffffffffu, s0, 8);
                s1 += __shfl_xor_sync(0xffffffffu, s1, 8);
                s2 += __shfl_xor_sync(0xffffffffu, s2, 8);
                s3 += __shfl_xor_sync(0xffffffffu, s3, 8);
                s0 += __shfl_xor_sync(0xffffffffu, s0, 16);
                s1 += __shfl_xor_sync(0xffffffffu, s1, 16);
                s2 += __shfl_xor_sync(0xffffffffu, s2, 16);
                s3 += __shfl_xor_sync(0xffffffffu, s3, 16);
                float f = (q == 0) ? s0 : (q == 1) ? s1 : (q == 2) ? s2 : s3;
                f += b3s[c3];
                int idx = q*64 + c3;
                int idz = q*64 + c3z;
                float yv = ys_[idx];
                if(e == 0){
                    kc[idx] = f;
                    zrow[idz] = yv + 0.5f*hs*f;
                } else if(e == 1){
                    kc[idx] += 2.0f*f;
                    zrow[idz] = yv + 0.5f*hs*f;
                } else if(e == 2){
                    kc[idx] += 2.0f*f;
                    zrow[idz] = yv + hs*f;
                } else {
                    float yn = yv + (hs/6.0f)*(kc[idx] + f);
                    ys_[idx] = yn;
                    zrow[idz] = yn;
                    g_ys[((size_t)(step+1)*BB + b0 + q)*LATD + c3] = yn;
                }
            }
            __syncthreads();
        }
    }
}

// ------------------------ interp helper -------------------------------------
__device__ __forceinline__ void interp_coeff(float qt, int nit, int* gi_out, float* w_out){
    int lo = 0, hi = nit;
    while(lo < hi){
        int mid = (lo + hi) >> 1;
        if(g_grid[mid] <= qt) lo = mid + 1; else hi = mid;
    }
    int gi = lo - 1;
    gi = max(0, min(gi, nit-2));
    float tl = g_grid[gi], tr = g_grid[gi+1];
    float den = tr - tl; if(den == 0.0f) den = 1.0f;
    *gi_out = gi;
    *w_out = (qt - tl) / den;
}

// ------------------------ k8: recon loss ------------------------------------
__global__ __launch_bounds__(128) void k_recon(const float* __restrict__ Wo1,
                                               const float* __restrict__ bo1,
                                               const float* __restrict__ Wo2,
                                               const float* __restrict__ bo2,
                                               const float* __restrict__ obs,
                                               const void* __restrict__ maskp,
                                               const int* __restrict__ tp,
                                               const int* __restrict__ seq_lens){
    extern __shared__ float sm[];
    float* wo1s = sm;                 // 64*128
    float* wo2s = wo1s + 64*128;      // 128*32
    float* bo1s = wo2s + 128*32;      // 128
    float* bo2s = bo1s + 128;         // 32
    float* zs   = bo2s + 32;          // 64*64
    float* h1s  = zs + TT*LATD;       // 128
    float* tw   = h1s + 128;          // 64
    int*   tgi  = (int*)(tw + TT);    // 64
    int tid = threadIdx.x, b = blockIdx.x;
    int mode = g_maskmode;
    for(int i = tid; i < 64*128; i += 128) wo1s[i] = Wo1[i];
    for(int i = tid; i < 128*32; i += 128) wo2s[i] = Wo2[i];
    bo1s[tid] = bo1[tid];
    if(tid < 32) bo2s[tid] = bo2[tid];
    int nit = g_niters;
    if(tid < TT){
        int v = tp[b*TT + tid];
        v = min(max(v, 0), TMAXV-1);
        float qt = g_qt[g_rank[v]];
        int gi; float w;
        interp_coeff(qt, nit, &gi, &w);
        tgi[tid] = gi; tw[tid] = w;
    }
    __syncthreads();
    for(int i = tid; i < TT*LATD; i += 128){
        int t = i >> 6, l = i & 63;
        int gi = tgi[t]; float w = tw[t];
        float zl = g_ys[((size_t)gi*BB + b)*LATD + l];
        float zr = g_ys[((size_t)(gi+1)*BB + b)*LATD + l];
        zs[i] = zl*(1.0f - w) + zr*w;
    }
    __syncthreads();
    int sl = seq_lens[b];
    if(sl > TT) sl = TT;
    double lsse = 0.0; float lnm = 0.0f;
    for(int t = 0; t < sl; t++){
        float acc = bo1s[tid];
        #pragma unroll 8
        for(int k = 0; k < 64; k++) acc = fmaf(zs[t*64+k], wo1s[k*128 + tid], acc);
        h1s[tid] = fmaxf(acc, 0.0f);
        __syncthreads();
        if(tid < NLL){
            float o = bo2s[tid];
            #pragma unroll 8
            for(int k = 0; k < 128; k++) o = fmaf(h1s[k], wo2s[k*32 + tid], o);
            float m = mread(maskp, (size_t)(b*TT + t)*NLL + tid, mode);
            float d = o - obs[(size_t)(b*TT + t)*NLL + tid];
            lsse += (double)(m*d*d);
            lnm  += m;
        }
        __syncthreads();
    }
    if(tid < 32){
        #pragma unroll
        for(int o = 16; o > 0; o >>= 1){
            lsse += __shfl_down_sync(0xffffffffu, lsse, o);
            lnm  += __shfl_down_sync(0xffffffffu, lnm,  o);
        }
        if(tid == 0){
            atomicAdd(&g_sse, lsse);
            atomicAdd(&g_nobs, (double)lnm);
        }
    }
}

// ------------------------ k9: z_eval + hazard -------------------------------
__global__ __launch_bounds__(128) void k_hazard(const float* __restrict__ Ws1,
                                                const float* __restrict__ bs1,
                                                const float* __restrict__ Ws2,
                                                const float* __restrict__ bs2,
                                                const float* __restrict__ age,
                                                const int* __restrict__ tp,
                                                const int* __restrict__ seq_lens,
                                                float* __restrict__ out){
    __shared__ float zev[DIN];    // z_eval (64) + age (1)
    __shared__ float hbuf[HIDD];
    int tid = threadIdx.x, b = blockIdx.x;
    int nit = g_niters;
    int sl = seq_lens[b];
    if(sl < 1) sl = 1; if(sl > TT) sl = TT;
    int v = tp[b*TT + sl - 1];
    v = min(max(v, 0), TMAXV-1);
    float qt = g_qt[g_rank[v]];
    int gi; float w;
    interp_coeff(qt, nit, &gi, &w);
    if(tid < LATD){
        float zl = g_ys[((size_t)gi*BB + b)*LATD + tid];
        float zr = g_ys[((size_t)(gi+1)*BB + b)*LATD + tid];
        float z = zl*(1.0f - w) + zr*w;
        zev[tid] = z;
        out[1026 + b*LATD + tid] = z;   // z_eval output
    }
    if(tid == 0) zev[LATD] = age[b];
    __syncthreads();
    float acc = bs1[tid];
    #pragma unroll 8
    for(int k = 0; k < DIN; k++) acc = fmaf(zev[k], Ws1[k*HIDD + tid], acc);
    hbuf[tid] = fmaxf(acc, 0.0f);
    __syncthreads();
    if(tid < 2){
        float o = bs2[tid];
        #pragma unroll 8
        for(int k = 0; k < HIDD; k++) o = fmaf(hbuf[k], Ws2[k*2 + tid], o);
        out[b*2 + tid] = o;             // log_hazard output
    }
}

// ------------------------ k10: write scalars --------------------------------
__global__ void k_final(float* __restrict__ out){
    if(threadIdx.x == 0){
        double n = g_nobs;
        out[1024] = (n > 0.0) ? (float)(g_sse / fmax(n, 1.0)) : 0.0f;   // recon
        out[1025] = (float)(-0.5 * g_kl / (double)BB);                   // kl
    }
}

// ------------------------ launch --------------------------------------------
extern "C" void kernel_launch(void* const* d_in, const int* in_sizes, int n_in,
                              void* d_out, int out_size){
    (void)in_sizes; (void)n_in; (void)out_size;
    const float* obs = (const float*)d_in[0];
    const float* age = (const float*)d_in[1];
    const float* eps = (const float*)d_in[2];
    const float* Wih = (const float*)d_in[3];
    const float* Whh = (const float*)d_in[4];
    const float* bih = (const float*)d_in[5];
    const float* bhh = (const float*)d_in[6];
    const float* Wmu = (const float*)d_in[7];
    const float* bmu = (const float*)d_in[8];
    const float* Wlv = (const float*)d_in[9];
    const float* blv = (const float*)d_in[10];
    const float* W1  = (const float*)d_in[11];
    const float* b1  = (const float*)d_in[12];
    const float* W2  = (const float*)d_in[13];
    const float* b2  = (const float*)d_in[14];
    const float* W3  = (const float*)d_in[15];
    const float* b3  = (const float*)d_in[16];
    const float* Wo1 = (const float*)d_in[17];
    const float* bo1 = (const float*)d_in[18];
    const float* Wo2 = (const float*)d_in[19];
    const float* bo2 = (const float*)d_in[20];
    const float* Ws1 = (const float*)d_in[21];
    const float* bs1 = (const float*)d_in[22];
    const float* Ws2 = (const float*)d_in[23];
    const float* bs2 = (const float*)d_in[24];
    const void*  msk = d_in[25];
    const int*   tp  = (const int*)d_in[26];
    const int*   seq = (const int*)d_in[27];
    float* out = (float*)d_out;

    const int GRU_SMEM = GRU_SMEM_BYTES;
    const int RK4_SMEM = RK4_SMEM_BYTES;
    const int REC_SMEM = (64*128 + 128*32 + 128 + 32 + TT*LATD + 128 + TT)*4
                         + TT*4;

    cudaFuncSetAttribute(k_gru,   cudaFuncAttributeMaxDynamicSharedMemorySize, GRU_SMEM);
    cudaFuncSetAttribute(k_rk4,   cudaFuncAttributeMaxDynamicSharedMemorySize, RK4_SMEM);
    cudaFuncSetAttribute(k_recon, cudaFuncAttributeMaxDynamicSharedMemorySize, REC_SMEM);

    k_zerodetect<<<9, 256>>>(msk);
    k_mark  <<<(BB*TT + 255)/256, 256>>>(tp);
    k_build <<<1, 256>>>();
    k_gi    <<<BB*TT/GITILE, 384>>>(obs, msk, tp, Wih, bih);
    k_gru   <<<BB/4, 384, GRU_SMEM>>>(Whh, bhh);
    k_latent<<<BB, 64>>>(Wmu, bmu, Wlv, blv, eps);
    k_rk4   <<<BB/4, 256, RK4_SMEM>>>(W1, b1, W2, b2, W3, b3);
    k_recon <<<BB, 128, REC_SMEM>>>(Wo1, bo1, Wo2, bo2, obs, msk, tp, seq);
    k_hazard<<<BB, 128>>>(Ws1, bs1, Ws2, bs2, age, tp, seq, out);
    k_final <<<1, 32>>>(out);
}